// round 6
// baseline (speedup 1.0000x reference)
#include <cuda_runtime.h>

#define B_     16
#define T_     65536
#define CHUNKS 128
#define L_     512
#define TILE   128
#define NTIL   4
#define PB     132
#define HH     4096
typedef unsigned long long ull;

__device__ float g_u [(size_t)B_ * T_ * 64];
__device__ float g_bu[(size_t)B_ * T_ * 64];
__device__ float g_ends[B_ * CHUNKS * 64];
__device__ float g_carr[B_ * CHUNKS * 64];
__device__ float g_cX[64];      // layer-0: gam0 * (Bm0 @ Win)
__device__ float g_wlo[64];     // last layer: Wout @ Wl3
__device__ float g_aux[1];      // Wout . bl3
__device__ float g_wT[12 * HH]; // transposed weights [l][{C,W,Bnext}][k][n]

__device__ __forceinline__ void fma2(ull& d, ull a, ull b) {
    asm("fma.rn.f32x2 %0, %1, %2, %0;" : "+l"(d) : "l"(a), "l"(b));
}
__device__ __forceinline__ ull add2(ull a, ull b) {
    ull d; asm("add.rn.f32x2 %0, %1, %2;" : "=l"(d) : "l"(a), "l"(b)); return d;
}
__device__ __forceinline__ ull mul2(ull a, ull b) {
    ull d; asm("mul.rn.f32x2 %0, %1, %2;" : "=l"(d) : "l"(a), "l"(b)); return d;
}
__device__ __forceinline__ ull dup2(float x) {
    ull r; asm("mov.b64 %0, {%1, %1};" : "=l"(r) : "f"(x)); return r;
}
__device__ __forceinline__ float2 unp(ull p) {
    float2 r; asm("mov.b64 {%0, %1}, %2;" : "=f"(r.x), "=f"(r.y) : "l"(p)); return r;
}
__device__ __forceinline__ ull pk(float a, float b) {
    ull r; asm("mov.b64 %0, {%1, %2};" : "=l"(r) : "f"(a), "f"(b)); return r;
}

// 8tok x 8n register-tile GEMM over 64 k.
// BUF (smem): [k][128 tok], pitch PB, quads swizzled q ^ ((k>>2)&7).
// wt (GMEM, L1-resident): [k][n] pitch 64, coalesced + broadcast across CTAs.
__device__ __forceinline__ void gemm8x8(const float* __restrict__ BUF,
                                        const float* __restrict__ wt,
                                        int g_t, int g_n, ull acc[4][8]) {
#pragma unroll 4
    for (int k = 0; k < 64; k++) {
        const int m = (k >> 2) & 7;
        const float* r = BUF + k * PB;
        ulonglong2 a0 = *(const ulonglong2*)(r + 4 * ((2 * g_t) ^ m));
        ulonglong2 a1 = *(const ulonglong2*)(r + 4 * ((2 * g_t + 1) ^ m));
        float4 b0 = __ldg((const float4*)(wt + k * 64 + 4 * g_n));
        float4 b1 = __ldg((const float4*)(wt + k * 64 + 32 + 4 * g_n));
        ull ap[4] = {a0.x, a0.y, a1.x, a1.y};
        ull bb[8] = {dup2(b0.x), dup2(b0.y), dup2(b0.z), dup2(b0.w),
                     dup2(b1.x), dup2(b1.y), dup2(b1.z), dup2(b1.w)};
#pragma unroll
        for (int q = 0; q < 8; q++)
#pragma unroll
            for (int ii = 0; ii < 4; ii++) fma2(acc[ii][q], ap[ii], bb[q]);
    }
}

__device__ __forceinline__ void stile(float* __restrict__ BUF, int g_t, int g_n,
                                      const ull acc[4][8]) {
#pragma unroll
    for (int q = 0; q < 8; q++) {
        const int jq = (q < 4) ? 4 * g_n + q : 28 + 4 * g_n + q;
        const int mj = (jq >> 2) & 7;
        ulonglong2 v0; v0.x = acc[0][q]; v0.y = acc[1][q];
        ulonglong2 v1; v1.x = acc[2][q]; v1.y = acc[3][q];
        *(ulonglong2*)(BUF + jq * PB + 4 * ((2 * g_t) ^ mj)) = v0;
        *(ulonglong2*)(BUF + jq * PB + 4 * ((2 * g_t + 1) ^ mj)) = v1;
    }
}

template <int MODE>
__device__ __forceinline__ void ldu(ull up[4], const float* __restrict__ uin,
                                    size_t toff, int jq, int i0,
                                    const float* __restrict__ XS, float w) {
    if (MODE == 0) {
        ull wp = dup2(w);
        up[0] = mul2(wp, *(const ull*)(XS + i0));
        up[1] = mul2(wp, *(const ull*)(XS + i0 + 2));
        up[2] = mul2(wp, *(const ull*)(XS + i0 + 4));
        up[3] = mul2(wp, *(const ull*)(XS + i0 + 6));
    } else {
        const float* p = uin + toff + (size_t)jq * TILE + i0;
        ulonglong2 a = *(const ulonglong2*)p;
        ulonglong2 b = *(const ulonglong2*)(p + 4);
        up[0] = a.x; up[1] = a.y; up[2] = b.x; up[3] = b.y;
    }
}

// ---------------------------------------------------------------------------
// k_prep: cX (layer-0 Bu coefficient), WLO, Wout.bl3.
// ---------------------------------------------------------------------------
__global__ void __launch_bounds__(64)
k_prep(const float* __restrict__ Bm0, const float* __restrict__ ga0,
       const float* __restrict__ Win, const float* __restrict__ Wl3,
       const float* __restrict__ bl3, const float* __restrict__ Wout) {
    const int n = threadIdx.x;
    float a = 0.f;
#pragma unroll
    for (int k = 0; k < 64; k++) a = fmaf(Bm0[n * 64 + k], Win[k], a);
    g_cX[n] = expf(ga0[n]) * a;
    float w = 0.f;
#pragma unroll
    for (int j = 0; j < 64; j++) w = fmaf(Wout[j], Wl3[j * 64 + n], w);
    g_wlo[n] = w;
    if (n == 0) {
        float s = 0.f;
#pragma unroll
        for (int j = 0; j < 64; j++) s = fmaf(Wout[j], bl3[j], s);
        g_aux[0] = s;
    }
}

// ---------------------------------------------------------------------------
// k_prepw: transpose all weights once into g_wT [l][{C,W,Bnext}][k][n],
// gamma folded into the B matrices.
// ---------------------------------------------------------------------------
__global__ void __launch_bounds__(128)
k_prepw(const float* __restrict__ Cm, const float* __restrict__ Wl,
        const float* __restrict__ Bm, const float* __restrict__ ga) {
    const int b = blockIdx.x;
    const int l = b / 3, m = b % 3;
    if (m == 2 && l == 3) return;
    __shared__ float gam[64];
    const int tid = threadIdx.x;
    const float* src = (m == 0) ? Cm + l * HH
                     : (m == 1) ? Wl + l * HH
                                : Bm + (l + 1) * HH;
    float* dst = g_wT + b * HH;
    if (m == 2) {
        if (tid < 64) gam[tid] = expf(ga[(l + 1) * 64 + tid]);
        __syncthreads();
    }
    for (int idx = tid; idx < HH; idx += 128) {
        int n = idx >> 6, k = idx & 63;
        float v = src[n * 64 + k];
        if (m == 2) v *= gam[n];
        dst[k * 64 + n] = v;
    }
}

// ---------------------------------------------------------------------------
// k_init: layer-0 chunk end states (Bu0 is rank-1; never materialized).
// ---------------------------------------------------------------------------
__global__ void __launch_bounds__(128)
k_init(const float* __restrict__ x, float* __restrict__ ends,
       const float* __restrict__ nu_log) {
    __shared__ float xs[TILE];
    const int tid = threadIdx.x;
    const int bc = blockIdx.x;
    const long tokbase = (long)(bc / CHUNKS) * T_ + (long)(bc % CHUNKS) * L_;

    float A = 0.f, s = 0.f;
    if (tid < 64) A = expf(-expf(nu_log[tid]));
    for (int tl = 0; tl < NTIL; tl++) {
        __syncthreads();
        xs[tid] = x[tokbase + tl * TILE + tid];
        __syncthreads();
        if (tid < 64) {
#pragma unroll 8
            for (int t = 0; t < TILE; t++) s = fmaf(A, s, xs[t]);
        }
    }
    if (tid < 64) ends[bc * 64 + tid] = g_cX[tid] * s;
}

__global__ void k_combine(const float* __restrict__ ends,
                          float* __restrict__ carries,
                          const float* __restrict__ nu_log) {
    const int b = blockIdx.x, n = threadIdx.x;
    const float AL = expf(-expf(nu_log[n]) * (float)L_);
    float carry = 0.f;
#pragma unroll 8
    for (int c = 0; c < CHUNKS; c++) {
        carries[(b * CHUNKS + c) * 64 + n] = carry;
        carry = fmaf(AL, carry, ends[(b * CHUNKS + c) * 64 + n]);
    }
}

// ---------------------------------------------------------------------------
// Fused per-layer kernel. Weights read from g_wT (gmem, L1-resident).
// MODE 0: first layer. MODE 1: middle. MODE 2: last (Wout folded).
// REV: reverse chunk order for L2 reuse against producer.
// smem ~35KB -> 3 CTAs/SM (regs 3*128*168 <= 64K).
// ---------------------------------------------------------------------------
#define SM_BUF  0
#define SM_XS   8448
#define SM_DV   8576
#define SM_BL   8640
#define SM_W2   8704
#define SM_WLO  8768
#define SM_AUX  8832
#define SM_CX   8836
#define SMEMF   8900
#define SMEMB   (SMEMF * 4)

template <int MODE, int REV>
__global__ void __launch_bounds__(128, 3)
k_apply(const float* __restrict__ xin, const float* __restrict__ uin,
        float* __restrict__ uout, float* __restrict__ bu,
        const float* __restrict__ carr, float* __restrict__ ends,
        const float* __restrict__ wtC, const float* __restrict__ wtW,
        const float* __restrict__ wtB,
        const float* __restrict__ Dv, const float* __restrict__ bl,
        const float* __restrict__ nu_log, const float* __restrict__ Win,
        const float* __restrict__ Wout, const float* __restrict__ nu_nx) {
    extern __shared__ __align__(16) float sm[];
    float* BUF = sm + SM_BUF;
    float* XS  = sm + SM_XS;
    float* DVs = sm + SM_DV;
    float* BLs = sm + SM_BL;
    float* W2s = sm + SM_W2;
    float* WLO = sm + SM_WLO;
    float* AUX = sm + SM_AUX;
    float* CXs = sm + SM_CX;

    const int tid = threadIdx.x;
    const int g_t = tid >> 3, g_n = tid & 7;
    const int i0 = g_t * 8;
    const int bc = REV ? (int)(gridDim.x - 1 - blockIdx.x) : (int)blockIdx.x;
    const long tokbase = (long)(bc / CHUNKS) * T_ + (long)(bc % CHUNKS) * L_;

    if (tid < 64) {
        DVs[tid] = Dv[tid];
        BLs[tid] = bl[tid];
        W2s[tid] = (MODE == 0) ? Win[tid] : ((MODE == 2) ? Wout[tid] : 0.f);
        if (MODE == 0) CXs[tid] = g_cX[tid];
        if (MODE == 2) WLO[tid] = g_wlo[tid];
        if (MODE == 2 && tid == 0) AUX[0] = g_aux[0];
    }
    float A1 = 0.f, h = 0.f, A2 = 0.f, s = 0.f;
    if (tid < 64) {
        A1 = expf(-expf(nu_log[tid]));
        h = carr[bc * 64 + tid];
        if (MODE != 2) A2 = expf(-expf(nu_nx[tid]));
    }
    __syncthreads();

    for (int tl = 0; tl < NTIL; tl++) {
        __syncthreads();
        const size_t toff = ((size_t)bc * NTIL + tl) * (64 * TILE);
        const long tokb = tokbase + (long)tl * TILE;

        if (MODE == 0) {
            XS[tid] = xin[tokb + tid];
            __syncthreads();
#pragma unroll
            for (int it = 0; it < 16; it++) {
                int idx = it * 512 + tid * 4;
                int row = idx >> 7, col = idx & 127;
                float c = CXs[row];
                float4 v = make_float4(c * XS[col], c * XS[col + 1],
                                       c * XS[col + 2], c * XS[col + 3]);
                *(float4*)(BUF + row * PB +
                           4 * ((col >> 2) ^ ((row >> 2) & 7))) = v;
            }
        } else {
#pragma unroll
            for (int it = 0; it < 16; it++) {
                int idx = it * 512 + tid * 4;
                int row = idx >> 7, lq = (idx >> 2) & 31;
                *(float4*)(BUF + row * PB + 4 * (lq ^ ((row >> 2) & 7))) =
                    *(const float4*)(bu + toff + idx);
            }
        }
        __syncthreads();

        // sequential scan: BUF <- hprev
        if (tid < 64) {
            float* r = BUF + tid * PB;
            const int m = (tid >> 2) & 7;
#pragma unroll 8
            for (int q = 0; q < 32; q++) {
                float4* p = (float4*)(r + 4 * (q ^ m));
                float4 v = *p; float4 o;
                o.x = h; h = fmaf(A1, h, v.x);
                o.y = h; h = fmaf(A1, h, v.y);
                o.z = h; h = fmaf(A1, h, v.z);
                o.w = h; h = fmaf(A1, h, v.w);
                *p = o;
            }
        }
        __syncthreads();

        // GEMM1: y = hprev @ Cm^T ; z = tanh~(y + Dv*u)
        ull acc[4][8];
#pragma unroll
        for (int q = 0; q < 8; q++)
#pragma unroll
            for (int ii = 0; ii < 4; ii++) acc[ii][q] = 0ull;
        gemm8x8(BUF, wtC, g_t, g_n, acc);
#pragma unroll
        for (int q = 0; q < 8; q++) {
            const int jq = (q < 4) ? 4 * g_n + q : 28 + 4 * g_n + q;
            ull dvp = dup2(DVs[jq]);
            ull up[4];
            ldu<MODE>(up, uin, toff, jq, i0, XS, W2s[jq]);
#pragma unroll
            for (int ii = 0; ii < 4; ii++) {
                ull y = acc[ii][q];
                fma2(y, dvp, up[ii]);
                float2 f = unp(y);
                f.x = f.x * rsqrtf(fmaf(f.x, f.x, 1.0f));
                f.y = f.y * rsqrtf(fmaf(f.y, f.y, 1.0f));
                acc[ii][q] = pk(f.x, f.y);
            }
        }
        __syncthreads();
        stile(BUF, g_t, g_n, acc);   // BUF <- z
        __syncthreads();

        if (MODE == 2) {
            const int tq = tid >> 2, te = tid & 3;
            float rs = AUX[0];
            const float* up = uin + toff + tid;
#pragma unroll 8
            for (int k = 0; k < 64; k++) {
                float zv = BUF[k * PB + 4 * (tq ^ ((k >> 2) & 7)) + te];
                rs = fmaf(WLO[k], zv, rs);
                rs = fmaf(W2s[k], up[k * TILE], rs);
            }
            uout[tokb + tid] = rs;
            continue;
        }

        // GEMM2: o = z @ Wl^T + bl + u
        ull o2[4][8];
#pragma unroll
        for (int q = 0; q < 8; q++)
#pragma unroll
            for (int ii = 0; ii < 4; ii++) o2[ii][q] = 0ull;
        gemm8x8(BUF, wtW, g_t, g_n, o2);
#pragma unroll
        for (int q = 0; q < 8; q++) {
            const int jq = (q < 4) ? 4 * g_n + q : 28 + 4 * g_n + q;
            ull blp = dup2(BLs[jq]);
            ull up[4];
            ldu<MODE>(up, uin, toff, jq, i0, XS, W2s[jq]);
#pragma unroll
            for (int ii = 0; ii < 4; ii++)
                o2[ii][q] = add2(o2[ii][q], add2(up[ii], blp));
        }
        __syncthreads();
        stile(BUF, g_t, g_n, o2);    // BUF <- u_next
        __syncthreads();

        // stream u_next out + GEMM3: Bu_next = u_next @ (g*Bm)^T
#pragma unroll
        for (int it = 0; it < 16; it++) {
            int idx = it * 512 + tid * 4;
            int row = idx >> 7, lq = (idx >> 2) & 31;
            *(float4*)(uout + toff + idx) =
                *(const float4*)(BUF + row * PB + 4 * (lq ^ ((row >> 2) & 7)));
        }
        ull b3[4][8];
#pragma unroll
        for (int q = 0; q < 8; q++)
#pragma unroll
            for (int ii = 0; ii < 4; ii++) b3[ii][q] = 0ull;
        gemm8x8(BUF, wtB, g_t, g_n, b3);
        __syncthreads();
        stile(BUF, g_t, g_n, b3);    // BUF <- Bu_next
        __syncthreads();

#pragma unroll
        for (int it = 0; it < 16; it++) {
            int idx = it * 512 + tid * 4;
            int row = idx >> 7, lq = (idx >> 2) & 31;
            *(float4*)(bu + toff + idx) =
                *(const float4*)(BUF + row * PB + 4 * (lq ^ ((row >> 2) & 7)));
        }
        if (tid < 64) {
            const float* r = BUF + tid * PB;
            const int m = (tid >> 2) & 7;
#pragma unroll 8
            for (int q = 0; q < 32; q++) {
                float4 v = *(const float4*)(r + 4 * (q ^ m));
                s = fmaf(A2, s, v.x); s = fmaf(A2, s, v.y);
                s = fmaf(A2, s, v.z); s = fmaf(A2, s, v.w);
            }
        }
    }
    if (MODE != 2 && tid < 64) ends[bc * 64 + tid] = s;
}

// ---------------------------------------------------------------------------
extern "C" void kernel_launch(void* const* d_in, const int* in_sizes, int n_in,
                              void* d_out, int out_size) {
    (void)in_sizes; (void)n_in; (void)out_size;
    const float* x   = (const float*)d_in[0];
    const float* Win = (const float*)d_in[1];
    const float* nu  = (const float*)d_in[2];
    const float* ga  = (const float*)d_in[3];
    const float* Bm  = (const float*)d_in[4];
    const float* Cm  = (const float*)d_in[5];
    const float* Dv  = (const float*)d_in[6];
    const float* Wl  = (const float*)d_in[7];
    const float* bl  = (const float*)d_in[8];
    const float* Wo  = (const float*)d_in[9];
    float* out = (float*)d_out;

    float *u, *bu, *ends, *carr, *wT;
    cudaGetSymbolAddress((void**)&u, g_u);
    cudaGetSymbolAddress((void**)&bu, g_bu);
    cudaGetSymbolAddress((void**)&ends, g_ends);
    cudaGetSymbolAddress((void**)&carr, g_carr);
    cudaGetSymbolAddress((void**)&wT, g_wT);

    const dim3 grid(B_ * CHUNKS), blk(128);

    k_prep<<<1, 64>>>(Bm, ga, Win, Wl + 3 * HH, bl + 192, Wo);
    k_prepw<<<12, 128>>>(Cm, Wl, Bm, ga);
    k_init<<<grid, blk>>>(x, ends, nu);
    k_combine<<<B_, 64>>>(ends, carr, nu);
    k_apply<0,0><<<grid, blk, SMEMB>>>(x, u, u, bu, carr, ends,
                                       wT + 0 * HH, wT + 1 * HH, wT + 2 * HH,
                                       Dv, bl, nu, Win, Wo, nu + 64);
    k_combine<<<B_, 64>>>(ends, carr, nu + 64);
    k_apply<1,1><<<grid, blk, SMEMB>>>(x, u, u, bu, carr, ends,
                                       wT + 3 * HH, wT + 4 * HH, wT + 5 * HH,
                                       Dv + 64, bl + 64, nu + 64, Win, Wo,
                                       nu + 128);
    k_combine<<<B_, 64>>>(ends, carr, nu + 128);
    k_apply<1,0><<<grid, blk, SMEMB>>>(x, u, u, bu, carr, ends,
                                       wT + 6 * HH, wT + 7 * HH, wT + 8 * HH,
                                       Dv + 128, bl + 128, nu + 128, Win, Wo,
                                       nu + 192);
    k_combine<<<B_, 64>>>(ends, carr, nu + 192);
    k_apply<2,1><<<grid, blk, SMEMB>>>(x, u, out, bu, carr, ends,
                                       wT + 9 * HH, wT + 10 * HH, wT + 9 * HH,
                                       Dv + 192, bl + 192, nu + 192, Win, Wo,
                                       nu);
}

// round 8
// speedup vs baseline: 1.0539x; 1.0539x over previous
#include <cuda_runtime.h>
#include <cstdint>

#define B_     16
#define T_     65536
#define CHUNKS 128
#define L_     512
#define TILE   128
#define NTIL   4
#define PB     132
#define HH     4096
typedef unsigned long long ull;
typedef unsigned int u32;

__device__ float g_u [(size_t)B_ * T_ * 64];
__device__ float g_bu[(size_t)B_ * T_ * 64];
__device__ float g_ends[B_ * CHUNKS * 64];
__device__ float g_carr[B_ * CHUNKS * 64];
__device__ float g_cX[64];      // layer-0: gam0 * (Bm0 @ Win)
__device__ float g_wlo[64];     // last layer: Wout @ Wl3
__device__ float g_aux[1];      // Wout . bl3
__device__ float g_wT[12 * HH]; // transposed weights [l][{C,W,Bnext}][k][n]

__device__ __forceinline__ void fma2(ull& d, ull a, ull b) {
    asm("fma.rn.f32x2 %0, %1, %2, %0;" : "+l"(d) : "l"(a), "l"(b));
}
__device__ __forceinline__ ull add2(ull a, ull b) {
    ull d; asm("add.rn.f32x2 %0, %1, %2;" : "=l"(d) : "l"(a), "l"(b)); return d;
}
__device__ __forceinline__ ull mul2(ull a, ull b) {
    ull d; asm("mul.rn.f32x2 %0, %1, %2;" : "=l"(d) : "l"(a), "l"(b)); return d;
}
__device__ __forceinline__ ull dup2(float x) {
    ull r; asm("mov.b64 %0, {%1, %1};" : "=l"(r) : "f"(x)); return r;
}
__device__ __forceinline__ float2 unp(ull p) {
    float2 r; asm("mov.b64 {%0, %1}, %2;" : "=f"(r.x), "=f"(r.y) : "l"(p)); return r;
}
__device__ __forceinline__ ull pk(float a, float b) {
    ull r; asm("mov.b64 %0, {%1, %2};" : "=l"(r) : "f"(a), "f"(b)); return r;
}

// async 16KB weight stage: gmem [k][n] (pre-transposed) -> smem slot
__device__ __forceinline__ void stage16k(u32 dst, const float* __restrict__ src,
                                         int tid) {
#pragma unroll
    for (int j = 0; j < 8; j++) {
        asm volatile("cp.async.ca.shared.global [%0], [%1], 16;"
                     :: "r"(dst + tid * 16 + j * 2048),
                        "l"(src + tid * 4 + j * 512));
    }
    asm volatile("cp.async.commit_group;");
}
__device__ __forceinline__ void cpwait() {
    asm volatile("cp.async.wait_group 0;");
}

// 8tok x 8n register-tile GEMM over 64 k.
// BUF (smem): [k][128 tok], pitch PB, quads swizzled q ^ ((k>>2)&7).
// wt (smem slot): [k][n] pitch 64.
__device__ __forceinline__ void gemm8x8(const float* __restrict__ BUF,
                                        const float* __restrict__ wt,
                                        int g_t, int g_n, ull acc[4][8]) {
#pragma unroll 4
    for (int k = 0; k < 64; k++) {
        const int m = (k >> 2) & 7;
        const float* r = BUF + k * PB;
        ulonglong2 a0 = *(const ulonglong2*)(r + 4 * ((2 * g_t) ^ m));
        ulonglong2 a1 = *(const ulonglong2*)(r + 4 * ((2 * g_t + 1) ^ m));
        float4 b0 = *(const float4*)(wt + k * 64 + 4 * g_n);
        float4 b1 = *(const float4*)(wt + k * 64 + 32 + 4 * g_n);
        ull ap[4] = {a0.x, a0.y, a1.x, a1.y};
        ull bb[8] = {dup2(b0.x), dup2(b0.y), dup2(b0.z), dup2(b0.w),
                     dup2(b1.x), dup2(b1.y), dup2(b1.z), dup2(b1.w)};
#pragma unroll
        for (int q = 0; q < 8; q++)
#pragma unroll
            for (int ii = 0; ii < 4; ii++) fma2(acc[ii][q], ap[ii], bb[q]);
    }
}

__device__ __forceinline__ void stile(float* __restrict__ BUF, int g_t, int g_n,
                                      const ull acc[4][8]) {
#pragma unroll
    for (int q = 0; q < 8; q++) {
        const int jq = (q < 4) ? 4 * g_n + q : 28 + 4 * g_n + q;
        const int mj = (jq >> 2) & 7;
        ulonglong2 v0; v0.x = acc[0][q]; v0.y = acc[1][q];
        ulonglong2 v1; v1.x = acc[2][q]; v1.y = acc[3][q];
        *(ulonglong2*)(BUF + jq * PB + 4 * ((2 * g_t) ^ mj)) = v0;
        *(ulonglong2*)(BUF + jq * PB + 4 * ((2 * g_t + 1) ^ mj)) = v1;
    }
}

template <int MODE>
__device__ __forceinline__ void ldu(ull up[4], const float* __restrict__ uin,
                                    size_t toff, int jq, int i0,
                                    const float* __restrict__ XS, float w) {
    if (MODE == 0) {
        ull wp = dup2(w);
        up[0] = mul2(wp, *(const ull*)(XS + i0));
        up[1] = mul2(wp, *(const ull*)(XS + i0 + 2));
        up[2] = mul2(wp, *(const ull*)(XS + i0 + 4));
        up[3] = mul2(wp, *(const ull*)(XS + i0 + 6));
    } else {
        const float* p = uin + toff + (size_t)jq * TILE + i0;
        ulonglong2 a = *(const ulonglong2*)p;
        ulonglong2 b = *(const ulonglong2*)(p + 4);
        up[0] = a.x; up[1] = a.y; up[2] = b.x; up[3] = b.y;
    }
}

// ---------------------------------------------------------------------------
__global__ void __launch_bounds__(64)
k_prep(const float* __restrict__ Bm0, const float* __restrict__ ga0,
       const float* __restrict__ Win, const float* __restrict__ Wl3,
       const float* __restrict__ bl3, const float* __restrict__ Wout) {
    const int n = threadIdx.x;
    float a = 0.f;
#pragma unroll
    for (int k = 0; k < 64; k++) a = fmaf(Bm0[n * 64 + k], Win[k], a);
    g_cX[n] = expf(ga0[n]) * a;
    float w = 0.f;
#pragma unroll
    for (int j = 0; j < 64; j++) w = fmaf(Wout[j], Wl3[j * 64 + n], w);
    g_wlo[n] = w;
    if (n == 0) {
        float s = 0.f;
#pragma unroll
        for (int j = 0; j < 64; j++) s = fmaf(Wout[j], bl3[j], s);
        g_aux[0] = s;
    }
}

__global__ void __launch_bounds__(128)
k_prepw(const float* __restrict__ Cm, const float* __restrict__ Wl,
        const float* __restrict__ Bm, const float* __restrict__ ga) {
    const int b = blockIdx.x;
    const int l = b / 3, m = b % 3;
    if (m == 2 && l == 3) return;
    __shared__ float gam[64];
    const int tid = threadIdx.x;
    const float* src = (m == 0) ? Cm + l * HH
                     : (m == 1) ? Wl + l * HH
                                : Bm + (l + 1) * HH;
    float* dst = g_wT + b * HH;
    if (m == 2) {
        if (tid < 64) gam[tid] = expf(ga[(l + 1) * 64 + tid]);
        __syncthreads();
    }
    for (int idx = tid; idx < HH; idx += 128) {
        int n = idx >> 6, k = idx & 63;
        float v = src[n * 64 + k];
        if (m == 2) v *= gam[n];
        dst[k * 64 + n] = v;
    }
}

__global__ void __launch_bounds__(128)
k_init(const float* __restrict__ x, float* __restrict__ ends,
       const float* __restrict__ nu_log) {
    __shared__ float xs[TILE];
    const int tid = threadIdx.x;
    const int bc = blockIdx.x;
    const long tokbase = (long)(bc / CHUNKS) * T_ + (long)(bc % CHUNKS) * L_;

    float A = 0.f, s = 0.f;
    if (tid < 64) A = expf(-expf(nu_log[tid]));
    for (int tl = 0; tl < NTIL; tl++) {
        __syncthreads();
        xs[tid] = x[tokbase + tl * TILE + tid];
        __syncthreads();
        if (tid < 64) {
#pragma unroll 8
            for (int t = 0; t < TILE; t++) s = fmaf(A, s, xs[t]);
        }
    }
    if (tid < 64) ends[bc * 64 + tid] = g_cX[tid] * s;
}

__global__ void k_combine(const float* __restrict__ ends,
                          float* __restrict__ carries,
                          const float* __restrict__ nu_log) {
    const int b = blockIdx.x, n = threadIdx.x;
    const float AL = expf(-expf(nu_log[n]) * (float)L_);
    float carry = 0.f;
#pragma unroll 8
    for (int c = 0; c < CHUNKS; c++) {
        carries[(b * CHUNKS + c) * 64 + n] = carry;
        carry = fmaf(AL, carry, ends[(b * CHUNKS + c) * 64 + n]);
    }
}

// ---------------------------------------------------------------------------
// Fused per-layer kernel. Weights double-buffered through 2 smem slots via
// cp.async prefetch (hidden under the previous GEMM). smem ~67KB -> 3 CTAs/SM.
// ---------------------------------------------------------------------------
#define SM_BUF  0
#define SM_W    8448          // 2 slots x 4096 floats
#define SM_XS   16640
#define SM_DV   16768
#define SM_BL   16832
#define SM_W2   16896
#define SM_WLO  16960
#define SM_AUX  17024
#define SM_CX   17028
#define SMEMF   17100
#define SMEMB   (SMEMF * 4)

template <int MODE, int REV>
__global__ void __launch_bounds__(128, 3)
k_apply(const float* __restrict__ xin, const float* __restrict__ uin,
        float* __restrict__ uout, float* __restrict__ bu,
        const float* __restrict__ carr, float* __restrict__ ends,
        const float* __restrict__ wtC, const float* __restrict__ wtW,
        const float* __restrict__ wtB,
        const float* __restrict__ Dv, const float* __restrict__ bl,
        const float* __restrict__ nu_log, const float* __restrict__ Win,
        const float* __restrict__ Wout, const float* __restrict__ nu_nx) {
    extern __shared__ __align__(16) float sm[];
    float* BUF = sm + SM_BUF;
    float* WSL = sm + SM_W;
    float* XS  = sm + SM_XS;
    float* DVs = sm + SM_DV;
    float* BLs = sm + SM_BL;
    float* W2s = sm + SM_W2;
    float* WLO = sm + SM_WLO;
    float* AUX = sm + SM_AUX;
    float* CXs = sm + SM_CX;

    const int tid = threadIdx.x;
    const int g_t = tid >> 3, g_n = tid & 7;
    const int i0 = g_t * 8;
    const int bc = REV ? (int)(gridDim.x - 1 - blockIdx.x) : (int)blockIdx.x;
    const long tokbase = (long)(bc / CHUNKS) * T_ + (long)(bc % CHUNKS) * L_;
    const u32 wS0 = (u32)__cvta_generic_to_shared(WSL);

    // prologue: stage wtC into slot 0
    stage16k(wS0, wtC, tid);
    int cur = 0;

    if (tid < 64) {
        DVs[tid] = Dv[tid];
        BLs[tid] = bl[tid];
        W2s[tid] = (MODE == 0) ? Win[tid] : ((MODE == 2) ? Wout[tid] : 0.f);
        if (MODE == 0) CXs[tid] = g_cX[tid];
        if (MODE == 2) WLO[tid] = g_wlo[tid];
        if (MODE == 2 && tid == 0) AUX[0] = g_aux[0];
    }
    float A1 = 0.f, h = 0.f, A2 = 0.f, s = 0.f;
    if (tid < 64) {
        A1 = expf(-expf(nu_log[tid]));
        h = carr[bc * 64 + tid];
        if (MODE != 2) A2 = expf(-expf(nu_nx[tid]));
    }
    cpwait();
    __syncthreads();

    for (int tl = 0; tl < NTIL; tl++) {
        __syncthreads();
        const size_t toff = ((size_t)bc * NTIL + tl) * (64 * TILE);
        const long tokb = tokbase + (long)tl * TILE;

        if (MODE == 0) {
            XS[tid] = xin[tokb + tid];
            __syncthreads();
#pragma unroll
            for (int it = 0; it < 16; it++) {
                int idx = it * 512 + tid * 4;
                int row = idx >> 7, col = idx & 127;
                float c = CXs[row];
                float4 v = make_float4(c * XS[col], c * XS[col + 1],
                                       c * XS[col + 2], c * XS[col + 3]);
                *(float4*)(BUF + row * PB +
                           4 * ((col >> 2) ^ ((row >> 2) & 7))) = v;
            }
        } else {
#pragma unroll
            for (int it = 0; it < 16; it++) {
                int idx = it * 512 + tid * 4;
                int row = idx >> 7, lq = (idx >> 2) & 31;
                *(float4*)(BUF + row * PB + 4 * (lq ^ ((row >> 2) & 7))) =
                    *(const float4*)(bu + toff + idx);
            }
        }
        __syncthreads();

        // sequential scan: BUF <- hprev
        if (tid < 64) {
            float* r = BUF + tid * PB;
            const int m = (tid >> 2) & 7;
#pragma unroll 8
            for (int q = 0; q < 32; q++) {
                float4* p = (float4*)(r + 4 * (q ^ m));
                float4 v = *p; float4 o;
                o.x = h; h = fmaf(A1, h, v.x);
                o.y = h; h = fmaf(A1, h, v.y);
                o.z = h; h = fmaf(A1, h, v.z);
                o.w = h; h = fmaf(A1, h, v.w);
                *p = o;
            }
        }
        __syncthreads();

        // GEMM1: y = hprev @ Cm^T ; prefetch wtW into the idle slot
        if (MODE != 2) stage16k(wS0 + (cur ^ 1) * 16384, wtW, tid);
        ull acc[4][8];
#pragma unroll
        for (int q = 0; q < 8; q++)
#pragma unroll
            for (int ii = 0; ii < 4; ii++) acc[ii][q] = 0ull;
        gemm8x8(BUF, WSL + cur * 4096, g_t, g_n, acc);
#pragma unroll
        for (int q = 0; q < 8; q++) {
            const int jq = (q < 4) ? 4 * g_n + q : 28 + 4 * g_n + q;
            ull dvp = dup2(DVs[jq]);
            ull up[4];
            ldu<MODE>(up, uin, toff, jq, i0, XS, W2s[jq]);
#pragma unroll
            for (int ii = 0; ii < 4; ii++) {
                ull y = acc[ii][q];
                fma2(y, dvp, up[ii]);
                float2 f = unp(y);
                f.x = f.x * rsqrtf(fmaf(f.x, f.x, 1.0f));
                f.y = f.y * rsqrtf(fmaf(f.y, f.y, 1.0f));
                acc[ii][q] = pk(f.x, f.y);
            }
        }
        if (MODE != 2) cpwait();
        __syncthreads();
        stile(BUF, g_t, g_n, acc);   // BUF <- z
        __syncthreads();

        if (MODE == 2) {
            const int tq = tid >> 2, te = tid & 3;
            float rs = AUX[0];
            const float* up = uin + toff + tid;
#pragma unroll 8
            for (int k = 0; k < 64; k++) {
                float zv = BUF[k * PB + 4 * (tq ^ ((k >> 2) & 7)) + te];
                rs = fmaf(WLO[k], zv, rs);
                rs = fmaf(W2s[k], up[k * TILE], rs);
            }
            uout[tokb + tid] = rs;
            continue;
        }
        cur ^= 1;

        // GEMM2: o = z @ Wl^T + bl + u ; prefetch wtB
        stage16k(wS0 + (cur ^ 1) * 16384, wtB, tid);
        ull o2[4][8];
#pragma unroll
        for (int q = 0; q < 8; q++)
#pragma unroll
            for (int ii = 0; ii < 4; ii++) o2[ii][q] = 0ull;
        gemm8x8(BUF, WSL + cur * 4096, g_t, g_n, o2);
#pragma unroll
        for (int q = 0; q < 8; q++) {
            const int jq = (q < 4) ? 4 * g_n + q : 28 + 4 * g_n + q;
            ull blp = dup2(BLs[jq]);
            ull up[4];
            ldu<MODE>(up, uin, toff, jq, i0, XS, W2s[jq]);
#pragma unroll
            for (int ii = 0; ii < 4; ii++)
                o2[ii][q] = add2(o2[ii][q], add2(up[ii], blp));
        }
        cpwait();
        __syncthreads();
        stile(BUF, g_t, g_n, o2);    // BUF <- u_next
        __syncthreads();
        cur ^= 1;

        // stream u_next out + GEMM3: Bu_next = u_next @ (g*Bm)^T ; prefetch wtC
#pragma unroll
        for (int it = 0; it < 16; it++) {
            int idx = it * 512 + tid * 4;
            int row = idx >> 7, lq = (idx >> 2) & 31;
            *(float4*)(uout + toff + idx) =
                *(const float4*)(BUF + row * PB + 4 * (lq ^ ((row >> 2) & 7)));
        }
        stage16k(wS0 + (cur ^ 1) * 16384, wtC, tid);
        ull b3[4][8];
#pragma unroll
        for (int q = 0; q < 8; q++)
#pragma unroll
            for (int ii = 0; ii < 4; ii++) b3[ii][q] = 0ull;
        gemm8x8(BUF, WSL + cur * 4096, g_t, g_n, b3);
        cpwait();
        __syncthreads();
        stile(BUF, g_t, g_n, b3);    // BUF <- Bu_next
        __syncthreads();
        cur ^= 1;

#pragma unroll
        for (int it = 0; it < 16; it++) {
            int idx = it * 512 + tid * 4;
            int row = idx >> 7, lq = (idx >> 2) & 31;
            *(float4*)(bu + toff + idx) =
                *(const float4*)(BUF + row * PB + 4 * (lq ^ ((row >> 2) & 7)));
        }
        if (tid < 64) {
            const float* r = BUF + tid * PB;
            const int m = (tid >> 2) & 7;
#pragma unroll 8
            for (int q = 0; q < 32; q++) {
                float4 v = *(const float4*)(r + 4 * (q ^ m));
                s = fmaf(A2, s, v.x); s = fmaf(A2, s, v.y);
                s = fmaf(A2, s, v.z); s = fmaf(A2, s, v.w);
            }
        }
    }
    if (MODE != 2 && tid < 64) ends[bc * 64 + tid] = s;
}

// ---------------------------------------------------------------------------
extern "C" void kernel_launch(void* const* d_in, const int* in_sizes, int n_in,
                              void* d_out, int out_size) {
    (void)in_sizes; (void)n_in; (void)out_size;
    const float* x   = (const float*)d_in[0];
    const float* Win = (const float*)d_in[1];
    const float* nu  = (const float*)d_in[2];
    const float* ga  = (const float*)d_in[3];
    const float* Bm  = (const float*)d_in[4];
    const float* Cm  = (const float*)d_in[5];
    const float* Dv  = (const float*)d_in[6];
    const float* Wl  = (const float*)d_in[7];
    const float* bl  = (const float*)d_in[8];
    const float* Wo  = (const float*)d_in[9];
    float* out = (float*)d_out;

    float *u, *bu, *ends, *carr, *wT;
    cudaGetSymbolAddress((void**)&u, g_u);
    cudaGetSymbolAddress((void**)&bu, g_bu);
    cudaGetSymbolAddress((void**)&ends, g_ends);
    cudaGetSymbolAddress((void**)&carr, g_carr);
    cudaGetSymbolAddress((void**)&wT, g_wT);

    static int inited = 0;
    if (!inited) {
        cudaFuncSetAttribute(k_apply<0,0>, cudaFuncAttributeMaxDynamicSharedMemorySize, SMEMB);
        cudaFuncSetAttribute(k_apply<1,1>, cudaFuncAttributeMaxDynamicSharedMemorySize, SMEMB);
        cudaFuncSetAttribute(k_apply<1,0>, cudaFuncAttributeMaxDynamicSharedMemorySize, SMEMB);
        cudaFuncSetAttribute(k_apply<2,1>, cudaFuncAttributeMaxDynamicSharedMemorySize, SMEMB);
        inited = 1;
    }

    const dim3 grid(B_ * CHUNKS), blk(128);

    k_prep<<<1, 64>>>(Bm, ga, Win, Wl + 3 * HH, bl + 192, Wo);
    k_prepw<<<12, 128>>>(Cm, Wl, Bm, ga);
    k_init<<<grid, blk>>>(x, ends, nu);
    k_combine<<<B_, 64>>>(ends, carr, nu);
    k_apply<0,0><<<grid, blk, SMEMB>>>(x, u, u, bu, carr, ends,
                                       wT + 0 * HH, wT + 1 * HH, wT + 2 * HH,
                                       Dv, bl, nu, Win, Wo, nu + 64);
    k_combine<<<B_, 64>>>(ends, carr, nu + 64);
    k_apply<1,1><<<grid, blk, SMEMB>>>(x, u, u, bu, carr, ends,
                                       wT + 3 * HH, wT + 4 * HH, wT + 5 * HH,
                                       Dv + 64, bl + 64, nu + 64, Win, Wo,
                                       nu + 128);
    k_combine<<<B_, 64>>>(ends, carr, nu + 128);
    k_apply<1,0><<<grid, blk, SMEMB>>>(x, u, u, bu, carr, ends,
                                       wT + 6 * HH, wT + 7 * HH, wT + 8 * HH,
                                       Dv + 128, bl + 128, nu + 128, Win, Wo,
                                       nu + 192);
    k_combine<<<B_, 64>>>(ends, carr, nu + 192);
    k_apply<2,1><<<grid, blk, SMEMB>>>(x, u, out, bu, carr, ends,
                                       wT + 9 * HH, wT + 9 * HH, wT + 9 * HH,
                                       Dv + 192, bl + 192, nu + 192, Win, Wo,
                                       nu);
}

// round 9
// speedup vs baseline: 1.0587x; 1.0045x over previous
#include <cuda_runtime.h>
#include <cstdint>

#define B_     16
#define T_     65536
#define CHUNKS 128
#define L_     512
#define TILE   128
#define NTIL   4
#define PB     132
#define HH     4096
typedef unsigned long long ull;
typedef unsigned int u32;

__device__ float g_u [(size_t)B_ * T_ * 64];
__device__ float g_bu[(size_t)B_ * T_ * 64];
__device__ float g_ends[B_ * CHUNKS * 64];
__device__ float g_carr[B_ * CHUNKS * 64];
__device__ float g_cX[64];      // layer-0: gam0 * (Bm0 @ Win)
__device__ float g_wlo[64];     // last layer: Wout @ Wl3
__device__ float g_aux[1];      // Wout . bl3
__device__ float g_wT[12 * HH]; // transposed weights [l][{C,W,Bnext}][k][n]

__device__ __forceinline__ void fma2(ull& d, ull a, ull b) {
    asm("fma.rn.f32x2 %0, %1, %2, %0;" : "+l"(d) : "l"(a), "l"(b));
}
__device__ __forceinline__ ull add2(ull a, ull b) {
    ull d; asm("add.rn.f32x2 %0, %1, %2;" : "=l"(d) : "l"(a), "l"(b)); return d;
}
__device__ __forceinline__ ull mul2(ull a, ull b) {
    ull d; asm("mul.rn.f32x2 %0, %1, %2;" : "=l"(d) : "l"(a), "l"(b)); return d;
}
__device__ __forceinline__ ull dup2(float x) {
    ull r; asm("mov.b64 %0, {%1, %1};" : "=l"(r) : "f"(x)); return r;
}
__device__ __forceinline__ float2 unp(ull p) {
    float2 r; asm("mov.b64 {%0, %1}, %2;" : "=f"(r.x), "=f"(r.y) : "l"(p)); return r;
}
__device__ __forceinline__ ull pk(float a, float b) {
    ull r; asm("mov.b64 %0, {%1, %2};" : "=l"(r) : "f"(a), "f"(b)); return r;
}

// async 16KB weight stage: gmem [k][n] (pre-transposed) -> smem slot
__device__ __forceinline__ void stage16k(u32 dst, const float* __restrict__ src,
                                         int tid) {
#pragma unroll
    for (int j = 0; j < 8; j++) {
        asm volatile("cp.async.ca.shared.global [%0], [%1], 16;"
                     :: "r"(dst + tid * 16 + j * 2048),
                        "l"(src + tid * 4 + j * 512));
    }
    asm volatile("cp.async.commit_group;");
}
__device__ __forceinline__ void cpwait() {
    asm volatile("cp.async.wait_group 0;");
}

// 8tok x 8n register-tile GEMM over 64 k.
__device__ __forceinline__ void gemm8x8(const float* __restrict__ BUF,
                                        const float* __restrict__ wt,
                                        int g_t, int g_n, ull acc[4][8]) {
#pragma unroll 4
    for (int k = 0; k < 64; k++) {
        const int m = (k >> 2) & 7;
        const float* r = BUF + k * PB;
        ulonglong2 a0 = *(const ulonglong2*)(r + 4 * ((2 * g_t) ^ m));
        ulonglong2 a1 = *(const ulonglong2*)(r + 4 * ((2 * g_t + 1) ^ m));
        float4 b0 = *(const float4*)(wt + k * 64 + 4 * g_n);
        float4 b1 = *(const float4*)(wt + k * 64 + 32 + 4 * g_n);
        ull ap[4] = {a0.x, a0.y, a1.x, a1.y};
        ull bb[8] = {dup2(b0.x), dup2(b0.y), dup2(b0.z), dup2(b0.w),
                     dup2(b1.x), dup2(b1.y), dup2(b1.z), dup2(b1.w)};
#pragma unroll
        for (int q = 0; q < 8; q++)
#pragma unroll
            for (int ii = 0; ii < 4; ii++) fma2(acc[ii][q], ap[ii], bb[q]);
    }
}

__device__ __forceinline__ void stile(float* __restrict__ BUF, int g_t, int g_n,
                                      const ull acc[4][8]) {
#pragma unroll
    for (int q = 0; q < 8; q++) {
        const int jq = (q < 4) ? 4 * g_n + q : 28 + 4 * g_n + q;
        const int mj = (jq >> 2) & 7;
        ulonglong2 v0; v0.x = acc[0][q]; v0.y = acc[1][q];
        ulonglong2 v1; v1.x = acc[2][q]; v1.y = acc[3][q];
        *(ulonglong2*)(BUF + jq * PB + 4 * ((2 * g_t) ^ mj)) = v0;
        *(ulonglong2*)(BUF + jq * PB + 4 * ((2 * g_t + 1) ^ mj)) = v1;
    }
}

template <int MODE>
__device__ __forceinline__ void ldu(ull up[4], const float* __restrict__ uin,
                                    size_t toff, int jq, int i0,
                                    const float* __restrict__ XS, float w) {
    if (MODE == 0) {
        ull wp = dup2(w);
        up[0] = mul2(wp, *(const ull*)(XS + i0));
        up[1] = mul2(wp, *(const ull*)(XS + i0 + 2));
        up[2] = mul2(wp, *(const ull*)(XS + i0 + 4));
        up[3] = mul2(wp, *(const ull*)(XS + i0 + 6));
    } else {
        const float* p = uin + toff + (size_t)jq * TILE + i0;
        ulonglong2 a = *(const ulonglong2*)p;
        ulonglong2 b = *(const ulonglong2*)(p + 4);
        up[0] = a.x; up[1] = a.y; up[2] = b.x; up[3] = b.y;
    }
}

// ---------------------------------------------------------------------------
// k_prep: blocks 0..11 transpose weights into g_wT (gamma folded into B);
// block 12 computes cX / wlo / aux scalars.
// ---------------------------------------------------------------------------
__global__ void __launch_bounds__(128)
k_prep(const float* __restrict__ Cm, const float* __restrict__ Wl,
       const float* __restrict__ Bm, const float* __restrict__ ga,
       const float* __restrict__ Win, const float* __restrict__ bl,
       const float* __restrict__ Wout) {
    const int b = blockIdx.x;
    const int tid = threadIdx.x;
    if (b == 12) {
        if (tid < 64) {
            const int n = tid;
            float a = 0.f;
#pragma unroll
            for (int k = 0; k < 64; k++) a = fmaf(Bm[n * 64 + k], Win[k], a);
            g_cX[n] = expf(ga[n]) * a;
            float w = 0.f;
#pragma unroll
            for (int j = 0; j < 64; j++)
                w = fmaf(Wout[j], Wl[3 * HH + j * 64 + n], w);
            g_wlo[n] = w;
            if (n == 0) {
                float s = 0.f;
#pragma unroll
                for (int j = 0; j < 64; j++) s = fmaf(Wout[j], bl[192 + j], s);
                g_aux[0] = s;
            }
        }
        return;
    }
    const int l = b / 3, m = b % 3;
    if (m == 2 && l == 3) return;
    __shared__ float gam[64];
    const float* src = (m == 0) ? Cm + l * HH
                     : (m == 1) ? Wl + l * HH
                                : Bm + (l + 1) * HH;
    float* dst = g_wT + b * HH;
    if (m == 2) {
        if (tid < 64) gam[tid] = expf(ga[(l + 1) * 64 + tid]);
        __syncthreads();
    }
    for (int idx = tid; idx < HH; idx += 128) {
        int n = idx >> 6, k = idx & 63;
        float v = src[n * 64 + k];
        if (m == 2) v *= gam[n];
        dst[k * 64 + n] = v;
    }
}

__global__ void __launch_bounds__(128)
k_init(const float* __restrict__ x, float* __restrict__ ends,
       const float* __restrict__ nu_log) {
    __shared__ __align__(16) float xs[TILE];
    const int tid = threadIdx.x;
    const int bc = blockIdx.x;
    const long tokbase = (long)(bc / CHUNKS) * T_ + (long)(bc % CHUNKS) * L_;

    float A = 0.f, a4 = 0.f, s = 0.f;
    if (tid < 64) {
        A = expf(-expf(nu_log[tid]));
        float a2 = A * A; a4 = a2 * a2;
    }
    for (int tl = 0; tl < NTIL; tl++) {
        __syncthreads();
        xs[tid] = x[tokbase + tl * TILE + tid];
        __syncthreads();
        if (tid < 64) {
#pragma unroll 8
            for (int q = 0; q < 32; q++) {
                float4 v = *(const float4*)(xs + 4 * q);
                float p2 = fmaf(A, v.x, v.y);
                float p3 = fmaf(A, p2, v.z);
                float p4 = fmaf(A, p3, v.w);
                s = fmaf(a4, s, p4);
            }
        }
    }
    if (tid < 64) ends[bc * 64 + tid] = g_cX[tid] * s;
}

// ---------------------------------------------------------------------------
// k_combine: stage ends into smem (coalesced), then quad-Horner carry chain.
// ---------------------------------------------------------------------------
__global__ void __launch_bounds__(128)
k_combine(const float* __restrict__ ends, float* __restrict__ carries,
          const float* __restrict__ nu_log) {
    __shared__ float es[CHUNKS * 64];
    const int b = blockIdx.x;
    const int tid = threadIdx.x;
    for (int i = tid; i < CHUNKS * 64; i += 128)
        es[i] = ends[b * CHUNKS * 64 + i];
    __syncthreads();
    if (tid < 64) {
        const int n = tid;
        const float AL = expf(-expf(nu_log[n]) * (float)L_);
        float carry = 0.f;
#pragma unroll 8
        for (int c = 0; c < CHUNKS; c++) {
            carries[(b * CHUNKS + c) * 64 + n] = carry;
            carry = fmaf(AL, carry, es[c * 64 + n]);
        }
    }
}

// ---------------------------------------------------------------------------
// Fused per-layer kernel. Weights double-buffered via cp.async; quad-Horner
// scan (serial depth 32 FMA/tile). smem ~67KB -> 3 CTAs/SM.
// ---------------------------------------------------------------------------
#define SM_BUF  0
#define SM_W    8448          // 2 slots x 4096 floats
#define SM_XS   16640
#define SM_DV   16768
#define SM_BL   16832
#define SM_W2   16896
#define SM_WLO  16960
#define SM_AUX  17024
#define SM_CX   17028
#define SMEMF   17100
#define SMEMB   (SMEMF * 4)

template <int MODE, int REV>
__global__ void __launch_bounds__(128, 3)
k_apply(const float* __restrict__ xin, const float* __restrict__ uin,
        float* __restrict__ uout, float* __restrict__ bu,
        const float* __restrict__ carr, float* __restrict__ ends,
        const float* __restrict__ wtC, const float* __restrict__ wtW,
        const float* __restrict__ wtB,
        const float* __restrict__ Dv, const float* __restrict__ bl,
        const float* __restrict__ nu_log, const float* __restrict__ Win,
        const float* __restrict__ Wout, const float* __restrict__ nu_nx) {
    extern __shared__ __align__(16) float sm[];
    float* BUF = sm + SM_BUF;
    float* WSL = sm + SM_W;
    float* XS  = sm + SM_XS;
    float* DVs = sm + SM_DV;
    float* BLs = sm + SM_BL;
    float* W2s = sm + SM_W2;
    float* WLO = sm + SM_WLO;
    float* AUX = sm + SM_AUX;
    float* CXs = sm + SM_CX;

    const int tid = threadIdx.x;
    const int g_t = tid >> 3, g_n = tid & 7;
    const int i0 = g_t * 8;
    const int bc = REV ? (int)(gridDim.x - 1 - blockIdx.x) : (int)blockIdx.x;
    const long tokbase = (long)(bc / CHUNKS) * T_ + (long)(bc % CHUNKS) * L_;
    const u32 wS0 = (u32)__cvta_generic_to_shared(WSL);

    stage16k(wS0, wtC, tid);
    int cur = 0;

    if (tid < 64) {
        DVs[tid] = Dv[tid];
        BLs[tid] = bl[tid];
        W2s[tid] = (MODE == 0) ? Win[tid] : ((MODE == 2) ? Wout[tid] : 0.f);
        if (MODE == 0) CXs[tid] = g_cX[tid];
        if (MODE == 2) WLO[tid] = g_wlo[tid];
        if (MODE == 2 && tid == 0) AUX[0] = g_aux[0];
    }
    float A1 = 0.f, a2 = 0.f, a3 = 0.f, a4 = 0.f, h = 0.f;
    float b4 = 0.f, A2n = 0.f, s = 0.f;
    if (tid < 64) {
        A1 = expf(-expf(nu_log[tid]));
        a2 = A1 * A1; a3 = a2 * A1; a4 = a2 * a2;
        h = carr[bc * 64 + tid];
        if (MODE != 2) {
            A2n = expf(-expf(nu_nx[tid]));
            float t2 = A2n * A2n; b4 = t2 * t2;
        }
    }
    cpwait();
    __syncthreads();

    for (int tl = 0; tl < NTIL; tl++) {
        __syncthreads();
        const size_t toff = ((size_t)bc * NTIL + tl) * (64 * TILE);
        const long tokb = tokbase + (long)tl * TILE;

        if (MODE == 0) {
            XS[tid] = xin[tokb + tid];
            __syncthreads();
#pragma unroll
            for (int it = 0; it < 16; it++) {
                int idx = it * 512 + tid * 4;
                int row = idx >> 7, col = idx & 127;
                float c = CXs[row];
                float4 v = make_float4(c * XS[col], c * XS[col + 1],
                                       c * XS[col + 2], c * XS[col + 3]);
                *(float4*)(BUF + row * PB +
                           4 * ((col >> 2) ^ ((row >> 2) & 7))) = v;
            }
        } else {
#pragma unroll
            for (int it = 0; it < 16; it++) {
                int idx = it * 512 + tid * 4;
                int row = idx >> 7, lq = (idx >> 2) & 31;
                *(float4*)(BUF + row * PB + 4 * (lq ^ ((row >> 2) & 7))) =
                    *(const float4*)(bu + toff + idx);
            }
        }
        __syncthreads();

        // quad-Horner scan: BUF <- hprev (serial depth: 1 FMA per quad)
        if (tid < 64) {
            float* r = BUF + tid * PB;
            const int m = (tid >> 2) & 7;
#pragma unroll 8
            for (int q = 0; q < 32; q++) {
                float4* p = (float4*)(r + 4 * (q ^ m));
                float4 v = *p; float4 o;
                float p2 = fmaf(A1, v.x, v.y);
                float p3 = fmaf(A1, p2, v.z);
                float p4 = fmaf(A1, p3, v.w);
                o.x = h;
                o.y = fmaf(A1, h, v.x);
                o.z = fmaf(a2, h, p2);
                o.w = fmaf(a3, h, p3);
                h   = fmaf(a4, h, p4);
                *p = o;
            }
        }
        __syncthreads();

        // GEMM1: y = hprev @ Cm^T ; prefetch wtW
        if (MODE != 2) stage16k(wS0 + (cur ^ 1) * 16384, wtW, tid);
        ull acc[4][8];
#pragma unroll
        for (int q = 0; q < 8; q++)
#pragma unroll
            for (int ii = 0; ii < 4; ii++) acc[ii][q] = 0ull;
        gemm8x8(BUF, WSL + cur * 4096, g_t, g_n, acc);
#pragma unroll
        for (int q = 0; q < 8; q++) {
            const int jq = (q < 4) ? 4 * g_n + q : 28 + 4 * g_n + q;
            ull dvp = dup2(DVs[jq]);
            ull up[4];
            ldu<MODE>(up, uin, toff, jq, i0, XS, W2s[jq]);
#pragma unroll
            for (int ii = 0; ii < 4; ii++) {
                ull y = acc[ii][q];
                fma2(y, dvp, up[ii]);
                float2 f = unp(y);
                f.x = f.x * rsqrtf(fmaf(f.x, f.x, 1.0f));
                f.y = f.y * rsqrtf(fmaf(f.y, f.y, 1.0f));
                acc[ii][q] = pk(f.x, f.y);
            }
        }
        if (MODE != 2) cpwait();
        __syncthreads();
        stile(BUF, g_t, g_n, acc);   // BUF <- z
        __syncthreads();

        if (MODE == 2) {
            const int tq = tid >> 2, te = tid & 3;
            float rs = AUX[0];
            const float* up = uin + toff + tid;
#pragma unroll 8
            for (int k = 0; k < 64; k++) {
                float zv = BUF[k * PB + 4 * (tq ^ ((k >> 2) & 7)) + te];
                rs = fmaf(WLO[k], zv, rs);
                rs = fmaf(W2s[k], up[k * TILE], rs);
            }
            uout[tokb + tid] = rs;
            continue;
        }
        cur ^= 1;

        // GEMM2: o = z @ Wl^T + bl + u ; prefetch wtB
        stage16k(wS0 + (cur ^ 1) * 16384, wtB, tid);
        ull o2[4][8];
#pragma unroll
        for (int q = 0; q < 8; q++)
#pragma unroll
            for (int ii = 0; ii < 4; ii++) o2[ii][q] = 0ull;
        gemm8x8(BUF, WSL + cur * 4096, g_t, g_n, o2);
#pragma unroll
        for (int q = 0; q < 8; q++) {
            const int jq = (q < 4) ? 4 * g_n + q : 28 + 4 * g_n + q;
            ull blp = dup2(BLs[jq]);
            ull up[4];
            ldu<MODE>(up, uin, toff, jq, i0, XS, W2s[jq]);
#pragma unroll
            for (int ii = 0; ii < 4; ii++)
                o2[ii][q] = add2(o2[ii][q], add2(up[ii], blp));
        }
        cpwait();
        __syncthreads();
        stile(BUF, g_t, g_n, o2);    // BUF <- u_next
        __syncthreads();
        cur ^= 1;

        // stream u_next out + GEMM3: Bu_next = u_next @ (g*Bm)^T ; prefetch wtC
#pragma unroll
        for (int it = 0; it < 16; it++) {
            int idx = it * 512 + tid * 4;
            int row = idx >> 7, lq = (idx >> 2) & 31;
            *(float4*)(uout + toff + idx) =
                *(const float4*)(BUF + row * PB + 4 * (lq ^ ((row >> 2) & 7)));
        }
        stage16k(wS0 + (cur ^ 1) * 16384, wtC, tid);
        ull b3[4][8];
#pragma unroll
        for (int q = 0; q < 8; q++)
#pragma unroll
            for (int ii = 0; ii < 4; ii++) b3[ii][q] = 0ull;
        gemm8x8(BUF, WSL + cur * 4096, g_t, g_n, b3);
        cpwait();
        __syncthreads();
        stile(BUF, g_t, g_n, b3);    // BUF <- Bu_next
        __syncthreads();
        cur ^= 1;

#pragma unroll
        for (int it = 0; it < 16; it++) {
            int idx = it * 512 + tid * 4;
            int row = idx >> 7, lq = (idx >> 2) & 31;
            *(float4*)(bu + toff + idx) =
                *(const float4*)(BUF + row * PB + 4 * (lq ^ ((row >> 2) & 7)));
        }
        // chunk end-state for next layer (quad-Horner, depth 1 FMA/quad)
        if (tid < 64) {
            const float* r = BUF + tid * PB;
            const int m = (tid >> 2) & 7;
#pragma unroll 8
            for (int q = 0; q < 32; q++) {
                float4 v = *(const float4*)(r + 4 * (q ^ m));
                float p2 = fmaf(A2n, v.x, v.y);
                float p3 = fmaf(A2n, p2, v.z);
                float p4 = fmaf(A2n, p3, v.w);
                s = fmaf(b4, s, p4);
            }
        }
    }
    if (MODE != 2 && tid < 64) ends[bc * 64 + tid] = s;
}

// ---------------------------------------------------------------------------
extern "C" void kernel_launch(void* const* d_in, const int* in_sizes, int n_in,
                              void* d_out, int out_size) {
    (void)in_sizes; (void)n_in; (void)out_size;
    const float* x   = (const float*)d_in[0];
    const float* Win = (const float*)d_in[1];
    const float* nu  = (const float*)d_in[2];
    const float* ga  = (const float*)d_in[3];
    const float* Bm  = (const float*)d_in[4];
    const float* Cm  = (const float*)d_in[5];
    const float* Dv  = (const float*)d_in[6];
    const float* Wl  = (const float*)d_in[7];
    const float* bl  = (const float*)d_in[8];
    const float* Wo  = (const float*)d_in[9];
    float* out = (float*)d_out;

    float *u, *bu, *ends, *carr, *wT;
    cudaGetSymbolAddress((void**)&u, g_u);
    cudaGetSymbolAddress((void**)&bu, g_bu);
    cudaGetSymbolAddress((void**)&ends, g_ends);
    cudaGetSymbolAddress((void**)&carr, g_carr);
    cudaGetSymbolAddress((void**)&wT, g_wT);

    static int inited = 0;
    if (!inited) {
        cudaFuncSetAttribute(k_apply<0,0>, cudaFuncAttributeMaxDynamicSharedMemorySize, SMEMB);
        cudaFuncSetAttribute(k_apply<1,1>, cudaFuncAttributeMaxDynamicSharedMemorySize, SMEMB);
        cudaFuncSetAttribute(k_apply<1,0>, cudaFuncAttributeMaxDynamicSharedMemorySize, SMEMB);
        cudaFuncSetAttribute(k_apply<2,1>, cudaFuncAttributeMaxDynamicSharedMemorySize, SMEMB);
        inited = 1;
    }

    const dim3 grid(B_ * CHUNKS), blk(128);

    k_prep<<<13, 128>>>(Cm, Wl, Bm, ga, Win, bl, Wo);
    k_init<<<grid, blk>>>(x, ends, nu);
    k_combine<<<B_, 128>>>(ends, carr, nu);
    k_apply<0,0><<<grid, blk, SMEMB>>>(x, u, u, bu, carr, ends,
                                       wT + 0 * HH, wT + 1 * HH, wT + 2 * HH,
                                       Dv, bl, nu, Win, Wo, nu + 64);
    k_combine<<<B_, 128>>>(ends, carr, nu + 64);
    k_apply<1,1><<<grid, blk, SMEMB>>>(x, u, u, bu, carr, ends,
                                       wT + 3 * HH, wT + 4 * HH, wT + 5 * HH,
                                       Dv + 64, bl + 64, nu + 64, Win, Wo,
                                       nu + 128);
    k_combine<<<B_, 128>>>(ends, carr, nu + 128);
    k_apply<1,0><<<grid, blk, SMEMB>>>(x, u, u, bu, carr, ends,
                                       wT + 6 * HH, wT + 7 * HH, wT + 8 * HH,
                                       Dv + 128, bl + 128, nu + 128, Win, Wo,
                                       nu + 192);
    k_combine<<<B_, 128>>>(ends, carr, nu + 192);
    k_apply<2,1><<<grid, blk, SMEMB>>>(x, u, out, bu, carr, ends,
                                       wT + 9 * HH, wT + 9 * HH, wT + 9 * HH,
                                       Dv + 192, bl + 192, nu + 192, Win, Wo,
                                       nu);
}

// round 10
// speedup vs baseline: 1.9192x; 1.8128x over previous
#include <cuda_runtime.h>
#include <cstdint>

#define B_     16
#define T_     65536
#define CHUNKS 128
#define L_     512
#define TILE   128
#define NTIL   4
#define PBN    68
#define HH     4096
typedef unsigned long long ull;
typedef unsigned int u32;

__device__ float g_u [(size_t)B_ * T_ * 64];
__device__ float g_bu[(size_t)B_ * T_ * 64];
__device__ float g_ends[B_ * CHUNKS * 64];
__device__ float g_carr[B_ * CHUNKS * 64];
__device__ float g_cX[64];
__device__ float g_wlo[64];
__device__ float g_aux[1];
__device__ float g_wT[12 * HH];   // fragment-packed tf32 weights

__device__ __forceinline__ void fma2(ull& d, ull a, ull b) {
    asm("fma.rn.f32x2 %0, %1, %2, %0;" : "+l"(d) : "l"(a), "l"(b));
}
__device__ __forceinline__ ull add2(ull a, ull b) {
    ull d; asm("add.rn.f32x2 %0, %1, %2;" : "=l"(d) : "l"(a), "l"(b)); return d;
}
__device__ __forceinline__ ull mul2(ull a, ull b) {
    ull d; asm("mul.rn.f32x2 %0, %1, %2;" : "=l"(d) : "l"(a), "l"(b)); return d;
}
__device__ __forceinline__ ull dup2(float x) {
    ull r; asm("mov.b64 %0, {%1, %1};" : "=l"(r) : "f"(x)); return r;
}
__device__ __forceinline__ float2 unp(ull p) {
    float2 r; asm("mov.b64 {%0, %1}, %2;" : "=f"(r.x), "=f"(r.y) : "l"(p)); return r;
}
__device__ __forceinline__ ull pk(float a, float b) {
    ull r; asm("mov.b64 %0, {%1, %2};" : "=l"(r) : "f"(a), "f"(b)); return r;
}
__device__ __forceinline__ u32 cvt_tf32(float x) {
    u32 r; asm("cvt.rna.tf32.f32 %0, %1;" : "=r"(r) : "f"(x)); return r;
}
__device__ __forceinline__ void mma_tf32(float* d, u32 a0, u32 a1, u32 a2,
                                         u32 a3, u32 b0, u32 b1) {
    asm volatile(
        "mma.sync.aligned.m16n8k8.row.col.f32.tf32.tf32.f32 "
        "{%0,%1,%2,%3}, {%4,%5,%6,%7}, {%8,%9}, {%0,%1,%2,%3};"
        : "+f"(d[0]), "+f"(d[1]), "+f"(d[2]), "+f"(d[3])
        : "r"(a0), "r"(a1), "r"(a2), "r"(a3), "r"(b0), "r"(b1));
}

// async 16KB weight stage (fragment-packed layout, linear copy)
__device__ __forceinline__ void stage16k(u32 dst, const float* __restrict__ src,
                                         int tid) {
#pragma unroll
    for (int j = 0; j < 8; j++) {
        asm volatile("cp.async.ca.shared.global [%0], [%1], 16;"
                     :: "r"(dst + tid * 16 + j * 2048),
                        "l"(src + tid * 4 + j * 512));
    }
    asm volatile("cp.async.commit_group;");
}
__device__ __forceinline__ void cpwait() {
    asm volatile("cp.async.wait_group 0;");
}

// mma GEMM over 64 k: out[t][n] = sum_k BUF[t][k] * M[n][k].
// BUF [t][n] pitch 68 (A-frag loads conflict-free); wt fragment-packed.
__device__ __forceinline__ void gemm_mma(const float* __restrict__ BUF,
                                         const float* __restrict__ wt,
                                         int tb0, int lq, int kcol, int lane,
                                         float acc[8][8]) {
#pragma unroll
    for (int s = 0; s < 8; s++) {
        const int kb = s * 8;
        u32 a[2][4];
#pragma unroll
        for (int mt = 0; mt < 2; mt++) {
            const float* p = BUF + (tb0 + 16 * mt + lq) * PBN + kb + kcol;
            a[mt][0] = cvt_tf32(p[0]);
            a[mt][1] = cvt_tf32(p[8 * PBN]);
            a[mt][2] = cvt_tf32(p[4]);
            a[mt][3] = cvt_tf32(p[8 * PBN + 4]);
        }
        const uint2* wp = (const uint2*)(wt + s * 512) + lane;
#pragma unroll
        for (int nt = 0; nt < 8; nt++) {
            uint2 b = wp[nt * 32];
            mma_tf32(&acc[nt][0], a[0][0], a[0][1], a[0][2], a[0][3], b.x, b.y);
            mma_tf32(&acc[nt][4], a[1][0], a[1][1], a[1][2], a[1][3], b.x, b.y);
        }
    }
}

// store D fragments into BUF [t][n]
__device__ __forceinline__ void stile_mma(float* __restrict__ BUF, int tb0,
                                          int lq, int kcol,
                                          const float acc[8][8]) {
#pragma unroll
    for (int nt = 0; nt < 8; nt++) {
        const int nc = nt * 8 + 2 * kcol;
#pragma unroll
        for (int mt = 0; mt < 2; mt++) {
            const int r0 = tb0 + 16 * mt + lq;
            *(ull*)(BUF + r0 * PBN + nc) = pk(acc[nt][4 * mt], acc[nt][4 * mt + 1]);
            *(ull*)(BUF + (r0 + 8) * PBN + nc) =
                pk(acc[nt][4 * mt + 2], acc[nt][4 * mt + 3]);
        }
    }
}

// ---------------------------------------------------------------------------
// k_prep: blocks 0..11 pack weights into mma B-fragment order (tf32-rounded,
// gamma folded into B matrices); block 12 computes cX / wlo / aux.
// frag value c: M[n = nt*8 + l/4][k = s*8 + (l&3) + 4c]
// ---------------------------------------------------------------------------
__global__ void __launch_bounds__(128)
k_prep(const float* __restrict__ Cm, const float* __restrict__ Wl,
       const float* __restrict__ Bm, const float* __restrict__ ga,
       const float* __restrict__ Win, const float* __restrict__ bl,
       const float* __restrict__ Wout) {
    const int b = blockIdx.x;
    const int tid = threadIdx.x;
    if (b == 12) {
        if (tid < 64) {
            const int n = tid;
            float a = 0.f;
#pragma unroll
            for (int k = 0; k < 64; k++) a = fmaf(Bm[n * 64 + k], Win[k], a);
            g_cX[n] = expf(ga[n]) * a;
            float w = 0.f;
#pragma unroll
            for (int j = 0; j < 64; j++)
                w = fmaf(Wout[j], Wl[3 * HH + j * 64 + n], w);
            g_wlo[n] = w;
            if (n == 0) {
                float s = 0.f;
#pragma unroll
                for (int j = 0; j < 64; j++) s = fmaf(Wout[j], bl[192 + j], s);
                g_aux[0] = s;
            }
        }
        return;
    }
    const int l = b / 3, m = b % 3;
    if (m == 2 && l == 3) return;
    __shared__ float gam[64];
    const float* src = (m == 0) ? Cm + l * HH
                     : (m == 1) ? Wl + l * HH
                                : Bm + (l + 1) * HH;
    u32* dst = (u32*)(g_wT + b * HH);
    if (m == 2) {
        if (tid < 64) gam[tid] = expf(ga[(l + 1) * 64 + tid]);
        __syncthreads();
    }
    for (int idx = tid; idx < HH; idx += 128) {
        const int c = idx & 1, ln = (idx >> 1) & 31;
        const int nt = (idx >> 6) & 7, s = idx >> 9;
        const int n = nt * 8 + (ln >> 2);
        const int k = s * 8 + (ln & 3) + 4 * c;
        float v = src[n * 64 + k];
        if (m == 2) v *= gam[n];
        dst[idx] = cvt_tf32(v);
    }
}

__global__ void __launch_bounds__(128)
k_init(const float* __restrict__ x, float* __restrict__ ends,
       const float* __restrict__ nu_log) {
    __shared__ __align__(16) float xs[TILE];
    const int tid = threadIdx.x;
    const int bc = blockIdx.x;
    const long tokbase = (long)(bc / CHUNKS) * T_ + (long)(bc % CHUNKS) * L_;

    float A = 0.f, a4 = 0.f, s = 0.f;
    if (tid < 64) {
        A = expf(-expf(nu_log[tid]));
        float a2 = A * A; a4 = a2 * a2;
    }
    for (int tl = 0; tl < NTIL; tl++) {
        __syncthreads();
        xs[tid] = x[tokbase + tl * TILE + tid];
        __syncthreads();
        if (tid < 64) {
#pragma unroll 8
            for (int q = 0; q < 32; q++) {
                float4 v = *(const float4*)(xs + 4 * q);
                float p2 = fmaf(A, v.x, v.y);
                float p3 = fmaf(A, p2, v.z);
                float p4 = fmaf(A, p3, v.w);
                s = fmaf(a4, s, p4);
            }
        }
    }
    if (tid < 64) ends[bc * 64 + tid] = g_cX[tid] * s;
}

__global__ void __launch_bounds__(128)
k_combine(const float* __restrict__ ends, float* __restrict__ carries,
          const float* __restrict__ nu_log) {
    __shared__ float es[CHUNKS * 64];
    const int b = blockIdx.x;
    const int tid = threadIdx.x;
    for (int i = tid; i < CHUNKS * 64; i += 128)
        es[i] = ends[b * CHUNKS * 64 + i];
    __syncthreads();
    if (tid < 64) {
        const int n = tid;
        const float AL = expf(-expf(nu_log[n]) * (float)L_);
        float carry = 0.f;
#pragma unroll 8
        for (int c = 0; c < CHUNKS; c++) {
            carries[(b * CHUNKS + c) * 64 + n] = carry;
            carry = fmaf(AL, carry, es[c * 64 + n]);
        }
    }
}

// ---------------------------------------------------------------------------
// Fused per-layer kernel, tensor-core GEMMs (mma.sync tf32).
// Activation tiles in gmem are [t][n] (t-major, 64 floats per row).
// ---------------------------------------------------------------------------
#define SM_BUF  0
#define SM_W    8704          // 2 slots x 4096 floats
#define SM_XS   16896
#define SM_DV   17024
#define SM_BL   17088
#define SM_W2   17152
#define SM_WLO  17216
#define SM_AUX  17280
#define SM_CX   17284
#define SMEMF   17348
#define SMEMB   (SMEMF * 4)

template <int MODE, int REV>
__global__ void __launch_bounds__(128, 3)
k_apply(const float* __restrict__ xin, const float* __restrict__ uin,
        float* __restrict__ uout, float* __restrict__ bu,
        const float* __restrict__ carr, float* __restrict__ ends,
        const float* __restrict__ wtC, const float* __restrict__ wtW,
        const float* __restrict__ wtB,
        const float* __restrict__ Dv, const float* __restrict__ bl,
        const float* __restrict__ nu_log, const float* __restrict__ Win,
        const float* __restrict__ Wout, const float* __restrict__ nu_nx) {
    extern __shared__ __align__(16) float sm[];
    float* BUF = sm + SM_BUF;
    float* WSL = sm + SM_W;
    float* XS  = sm + SM_XS;
    float* DVs = sm + SM_DV;
    float* BLs = sm + SM_BL;
    float* W2s = sm + SM_W2;
    float* WLO = sm + SM_WLO;
    float* AUX = sm + SM_AUX;
    float* CXs = sm + SM_CX;

    const int tid = threadIdx.x;
    const int lane = tid & 31;
    const int lq = lane >> 2, kcol = lane & 3;
    const int tb0 = (tid >> 5) * 32;
    const int bc = REV ? (int)(gridDim.x - 1 - blockIdx.x) : (int)blockIdx.x;
    const long tokbase = (long)(bc / CHUNKS) * T_ + (long)(bc % CHUNKS) * L_;
    const u32 wS0 = (u32)__cvta_generic_to_shared(WSL);

    stage16k(wS0, wtC, tid);
    int cur = 0;

    if (tid < 64) {
        DVs[tid] = Dv[tid];
        BLs[tid] = bl[tid];
        W2s[tid] = (MODE == 0) ? Win[tid] : ((MODE == 2) ? Wout[tid] : 0.f);
        if (MODE == 0) CXs[tid] = g_cX[tid];
        if (MODE == 2) WLO[tid] = g_wlo[tid];
        if (MODE == 2 && tid == 0) AUX[0] = g_aux[0];
    }
    float A1 = 0.f, a2 = 0.f, a3 = 0.f, a4 = 0.f, h = 0.f;
    float b4 = 0.f, A2n = 0.f, s = 0.f;
    if (tid < 64) {
        A1 = expf(-expf(nu_log[tid]));
        a2 = A1 * A1; a3 = a2 * A1; a4 = a2 * a2;
        h = carr[bc * 64 + tid];
        if (MODE != 2) {
            A2n = expf(-expf(nu_nx[tid]));
            float t2 = A2n * A2n; b4 = t2 * t2;
        }
    }
    cpwait();
    __syncthreads();

    for (int tl = 0; tl < NTIL; tl++) {
        __syncthreads();
        const size_t toff = ((size_t)bc * NTIL + tl) * (64 * TILE);
        const long tokb = tokbase + (long)tl * TILE;

        if (MODE == 0) {
            XS[tid] = xin[tokb + tid];
            __syncthreads();
#pragma unroll
            for (int it = 0; it < 16; it++) {
                int idx = it * 512 + tid * 4;
                int t = idx >> 6, n = idx & 63;
                float xv = XS[t];
                float4 c = *(const float4*)(CXs + n);
                float4 v = make_float4(xv * c.x, xv * c.y, xv * c.z, xv * c.w);
                *(float4*)(BUF + t * PBN + n) = v;
            }
        } else {
#pragma unroll
            for (int it = 0; it < 16; it++) {
                int idx = it * 512 + tid * 4;
                int t = idx >> 6, n = idx & 63;
                *(float4*)(BUF + t * PBN + n) = *(const float4*)(bu + toff + idx);
            }
        }
        __syncthreads();

        // quad-Horner scan over [t][n] columns: BUF <- hprev
        if (tid < 64) {
            float* p = BUF + tid;
#pragma unroll 4
            for (int q = 0; q < 32; q++) {
                float* r = p + 4 * q * PBN;
                float v0 = r[0], v1 = r[PBN], v2 = r[2 * PBN], v3 = r[3 * PBN];
                float p2 = fmaf(A1, v0, v1);
                float p3 = fmaf(A1, p2, v2);
                float p4 = fmaf(A1, p3, v3);
                r[0] = h;
                r[PBN] = fmaf(A1, h, v0);
                r[2 * PBN] = fmaf(a2, h, p2);
                r[3 * PBN] = fmaf(a3, h, p3);
                h = fmaf(a4, h, p4);
            }
        }
        __syncthreads();

        // GEMM1: y = hprev @ Cm^T ; prefetch wtW
        if (MODE != 2) stage16k(wS0 + (cur ^ 1) * 16384, wtW, tid);
        float acc[8][8];
#pragma unroll
        for (int nt = 0; nt < 8; nt++)
#pragma unroll
            for (int j = 0; j < 8; j++) acc[nt][j] = 0.f;
        gemm_mma(BUF, WSL + cur * 4096, tb0, lq, kcol, lane, acc);

        // epilogue: z = tanh~(y + Dv*u)
#pragma unroll
        for (int nt = 0; nt < 8; nt++) {
            const int nc = nt * 8 + 2 * kcol;
            const ull dv2 = *(const ull*)(DVs + nc);
#pragma unroll
            for (int mt = 0; mt < 2; mt++) {
                const int r0 = tb0 + 16 * mt + lq;
                ull u0, u1;
                if (MODE == 0) {
                    const ull w2 = *(const ull*)(W2s + nc);
                    u0 = mul2(dup2(XS[r0]), w2);
                    u1 = mul2(dup2(XS[r0 + 8]), w2);
                } else {
                    u0 = *(const ull*)(uin + toff + r0 * 64 + nc);
                    u1 = *(const ull*)(uin + toff + (r0 + 8) * 64 + nc);
                }
                ull y0 = pk(acc[nt][4 * mt], acc[nt][4 * mt + 1]);
                ull y1 = pk(acc[nt][4 * mt + 2], acc[nt][4 * mt + 3]);
                fma2(y0, dv2, u0);
                fma2(y1, dv2, u1);
                float2 f0 = unp(y0), f1 = unp(y1);
                acc[nt][4 * mt]     = f0.x * rsqrtf(fmaf(f0.x, f0.x, 1.0f));
                acc[nt][4 * mt + 1] = f0.y * rsqrtf(fmaf(f0.y, f0.y, 1.0f));
                acc[nt][4 * mt + 2] = f1.x * rsqrtf(fmaf(f1.x, f1.x, 1.0f));
                acc[nt][4 * mt + 3] = f1.y * rsqrtf(fmaf(f1.y, f1.y, 1.0f));
            }
        }
        if (MODE != 2) cpwait();
        __syncthreads();
        stile_mma(BUF, tb0, lq, kcol, acc);   // BUF <- z
        __syncthreads();

        if (MODE == 2) {
            // out[t] = AUX + WLO.z[t] + Wout.u[t]
            const float* zr = BUF + tid * PBN;
            const float* ur = uin + toff + tid * 64;
            float rs = AUX[0];
#pragma unroll 4
            for (int jj = 0; jj < 16; jj++) {
                float4 z4 = *(const float4*)(zr + 4 * jj);
                float4 u4 = *(const float4*)(ur + 4 * jj);
                float4 w4 = *(const float4*)(WLO + 4 * jj);
                float4 v4 = *(const float4*)(W2s + 4 * jj);
                rs = fmaf(z4.x, w4.x, rs); rs = fmaf(u4.x, v4.x, rs);
                rs = fmaf(z4.y, w4.y, rs); rs = fmaf(u4.y, v4.y, rs);
                rs = fmaf(z4.z, w4.z, rs); rs = fmaf(u4.z, v4.z, rs);
                rs = fmaf(z4.w, w4.w, rs); rs = fmaf(u4.w, v4.w, rs);
            }
            uout[tokb + tid] = rs;
            continue;
        }
        cur ^= 1;

        // GEMM2: o = z @ Wl^T + bl + u ; prefetch wtB
        stage16k(wS0 + (cur ^ 1) * 16384, wtB, tid);
#pragma unroll
        for (int nt = 0; nt < 8; nt++)
#pragma unroll
            for (int j = 0; j < 8; j++) acc[nt][j] = 0.f;
        gemm_mma(BUF, WSL + cur * 4096, tb0, lq, kcol, lane, acc);
#pragma unroll
        for (int nt = 0; nt < 8; nt++) {
            const int nc = nt * 8 + 2 * kcol;
            const ull bl2 = *(const ull*)(BLs + nc);
#pragma unroll
            for (int mt = 0; mt < 2; mt++) {
                const int r0 = tb0 + 16 * mt + lq;
                ull u0, u1;
                if (MODE == 0) {
                    const ull w2 = *(const ull*)(W2s + nc);
                    u0 = mul2(dup2(XS[r0]), w2);
                    u1 = mul2(dup2(XS[r0 + 8]), w2);
                } else {
                    u0 = *(const ull*)(uin + toff + r0 * 64 + nc);
                    u1 = *(const ull*)(uin + toff + (r0 + 8) * 64 + nc);
                }
                ull y0 = pk(acc[nt][4 * mt], acc[nt][4 * mt + 1]);
                ull y1 = pk(acc[nt][4 * mt + 2], acc[nt][4 * mt + 3]);
                y0 = add2(y0, add2(u0, bl2));
                y1 = add2(y1, add2(u1, bl2));
                float2 f0 = unp(y0), f1 = unp(y1);
                acc[nt][4 * mt] = f0.x;     acc[nt][4 * mt + 1] = f0.y;
                acc[nt][4 * mt + 2] = f1.x; acc[nt][4 * mt + 3] = f1.y;
            }
        }
        cpwait();
        __syncthreads();
        stile_mma(BUF, tb0, lq, kcol, acc);   // BUF <- u_next
        __syncthreads();
        cur ^= 1;

        // stream u_next out + GEMM3: Bu_next = u_next @ (g*Bm)^T ; prefetch wtC
#pragma unroll
        for (int it = 0; it < 16; it++) {
            int idx = it * 512 + tid * 4;
            int t = idx >> 6, n = idx & 63;
            *(float4*)(uout + toff + idx) = *(const float4*)(BUF + t * PBN + n);
        }
        stage16k(wS0 + (cur ^ 1) * 16384, wtC, tid);
#pragma unroll
        for (int nt = 0; nt < 8; nt++)
#pragma unroll
            for (int j = 0; j < 8; j++) acc[nt][j] = 0.f;
        gemm_mma(BUF, WSL + cur * 4096, tb0, lq, kcol, lane, acc);
        cpwait();
        __syncthreads();
        stile_mma(BUF, tb0, lq, kcol, acc);   // BUF <- Bu_next
        __syncthreads();
        cur ^= 1;

#pragma unroll
        for (int it = 0; it < 16; it++) {
            int idx = it * 512 + tid * 4;
            int t = idx >> 6, n = idx & 63;
            *(float4*)(bu + toff + idx) = *(const float4*)(BUF + t * PBN + n);
        }
        // chunk end-state for next layer (quad-Horner over columns)
        if (tid < 64) {
            const float* p = BUF + tid;
#pragma unroll 4
            for (int q = 0; q < 32; q++) {
                const float* r = p + 4 * q * PBN;
                float p2 = fmaf(A2n, r[0], r[PBN]);
                float p3 = fmaf(A2n, p2, r[2 * PBN]);
                float p4 = fmaf(A2n, p3, r[3 * PBN]);
                s = fmaf(b4, s, p4);
            }
        }
    }
    if (MODE != 2 && tid < 64) ends[bc * 64 + tid] = s;
}

// ---------------------------------------------------------------------------
extern "C" void kernel_launch(void* const* d_in, const int* in_sizes, int n_in,
                              void* d_out, int out_size) {
    (void)in_sizes; (void)n_in; (void)out_size;
    const float* x   = (const float*)d_in[0];
    const float* Win = (const float*)d_in[1];
    const float* nu  = (const float*)d_in[2];
    const float* ga  = (const float*)d_in[3];
    const float* Bm  = (const float*)d_in[4];
    const float* Cm  = (const float*)d_in[5];
    const float* Dv  = (const float*)d_in[6];
    const float* Wl  = (const float*)d_in[7];
    const float* bl  = (const float*)d_in[8];
    const float* Wo  = (const float*)d_in[9];
    float* out = (float*)d_out;

    float *u, *bu, *ends, *carr, *wT;
    cudaGetSymbolAddress((void**)&u, g_u);
    cudaGetSymbolAddress((void**)&bu, g_bu);
    cudaGetSymbolAddress((void**)&ends, g_ends);
    cudaGetSymbolAddress((void**)&carr, g_carr);
    cudaGetSymbolAddress((void**)&wT, g_wT);

    static int inited = 0;
    if (!inited) {
        cudaFuncSetAttribute(k_apply<0,0>, cudaFuncAttributeMaxDynamicSharedMemorySize, SMEMB);
        cudaFuncSetAttribute(k_apply<1,1>, cudaFuncAttributeMaxDynamicSharedMemorySize, SMEMB);
        cudaFuncSetAttribute(k_apply<1,0>, cudaFuncAttributeMaxDynamicSharedMemorySize, SMEMB);
        cudaFuncSetAttribute(k_apply<2,1>, cudaFuncAttributeMaxDynamicSharedMemorySize, SMEMB);
        inited = 1;
    }

    const dim3 grid(B_ * CHUNKS), blk(128);

    k_prep<<<13, 128>>>(Cm, Wl, Bm, ga, Win, bl, Wo);
    k_init<<<grid, blk>>>(x, ends, nu);
    k_combine<<<B_, 128>>>(ends, carr, nu);
    k_apply<0,0><<<grid, blk, SMEMB>>>(x, u, u, bu, carr, ends,
                                       wT + 0 * HH, wT + 1 * HH, wT + 2 * HH,
                                       Dv, bl, nu, Win, Wo, nu + 64);
    k_combine<<<B_, 128>>>(ends, carr, nu + 64);
    k_apply<1,1><<<grid, blk, SMEMB>>>(x, u, u, bu, carr, ends,
                                       wT + 3 * HH, wT + 4 * HH, wT + 5 * HH,
                                       Dv + 64, bl + 64, nu + 64, Win, Wo,
                                       nu + 128);
    k_combine<<<B_, 128>>>(ends, carr, nu + 128);
    k_apply<1,0><<<grid, blk, SMEMB>>>(x, u, u, bu, carr, ends,
                                       wT + 6 * HH, wT + 7 * HH, wT + 8 * HH,
                                       Dv + 128, bl + 128, nu + 128, Win, Wo,
                                       nu + 192);
    k_combine<<<B_, 128>>>(ends, carr, nu + 192);
    k_apply<2,1><<<grid, blk, SMEMB>>>(x, u, out, bu, carr, ends,
                                       wT + 9 * HH, wT + 9 * HH, wT + 9 * HH,
                                       Dv + 192, bl + 192, nu + 192, Win, Wo,
                                       nu);
}

// round 11
// speedup vs baseline: 2.2931x; 1.1949x over previous
#include <cuda_runtime.h>
#include <cstdint>

#define B_     16
#define T_     65536
#define CHUNKS 128
#define TILE   128
#define NTIL   4
#define L_     512
#define PBN    76
#define HH     4096
typedef unsigned long long ull;
typedef unsigned int u32;

__device__ float g_u [(size_t)B_ * T_ * 64];
__device__ float g_bu[(size_t)B_ * T_ * 64];
__device__ float g_ends[B_ * CHUNKS * 64];
__device__ float g_carr[B_ * CHUNKS * 64];
__device__ float g_cX[64];
__device__ float g_wlo[64];
__device__ float g_aux[1];
__device__ float g_wT[12 * HH];   // fragment-packed tf32 weights

__device__ __forceinline__ void fma2(ull& d, ull a, ull b) {
    asm("fma.rn.f32x2 %0, %1, %2, %0;" : "+l"(d) : "l"(a), "l"(b));
}
__device__ __forceinline__ ull add2(ull a, ull b) {
    ull d; asm("add.rn.f32x2 %0, %1, %2;" : "=l"(d) : "l"(a), "l"(b)); return d;
}
__device__ __forceinline__ ull mul2(ull a, ull b) {
    ull d; asm("mul.rn.f32x2 %0, %1, %2;" : "=l"(d) : "l"(a), "l"(b)); return d;
}
__device__ __forceinline__ ull dup2(float x) {
    ull r; asm("mov.b64 %0, {%1, %1};" : "=l"(r) : "f"(x)); return r;
}
__device__ __forceinline__ float2 unp(ull p) {
    float2 r; asm("mov.b64 {%0, %1}, %2;" : "=f"(r.x), "=f"(r.y) : "l"(p)); return r;
}
__device__ __forceinline__ ull pk(float a, float b) {
    ull r; asm("mov.b64 %0, {%1, %2};" : "=l"(r) : "f"(a), "f"(b)); return r;
}
__device__ __forceinline__ u32 cvt_tf32(float x) {
    u32 r; asm("cvt.rna.tf32.f32 %0, %1;" : "=r"(r) : "f"(x)); return r;
}
__device__ __forceinline__ void mma_tf32(float* d, u32 a0, u32 a1, u32 a2,
                                         u32 a3, u32 b0, u32 b1) {
    asm volatile(
        "mma.sync.aligned.m16n8k8.row.col.f32.tf32.tf32.f32 "
        "{%0,%1,%2,%3}, {%4,%5,%6,%7}, {%8,%9}, {%0,%1,%2,%3};"
        : "+f"(d[0]), "+f"(d[1]), "+f"(d[2]), "+f"(d[3])
        : "r"(a0), "r"(a1), "r"(a2), "r"(a3), "r"(b0), "r"(b1));
}

__device__ __forceinline__ void stage16k(u32 dst, const float* __restrict__ src,
                                         int tid) {
#pragma unroll
    for (int j = 0; j < 8; j++) {
        asm volatile("cp.async.ca.shared.global [%0], [%1], 16;"
                     :: "r"(dst + tid * 16 + j * 2048),
                        "l"(src + tid * 4 + j * 512));
    }
    asm volatile("cp.async.commit_group;");
}
__device__ __forceinline__ void cpwait() {
    asm volatile("cp.async.wait_group 0;");
}

// fragment-layout gmem offset: tile base toff, warp w, j = nt*2+mt, lane.
// float4 = {v[r0][nc], v[r0][nc+1], v[r0+8][nc], v[r0+8][nc+1]}
__device__ __forceinline__ size_t fragoff(size_t toff, int w, int j, int lane) {
    return toff + (size_t)w * 2048 + (size_t)(j * 32 + lane) * 4;
}

// mma GEMM over 64 k: out[t][n] = sum_k BUF[t][k] * M[n][k].
__device__ __forceinline__ void gemm_mma(const float* __restrict__ BUF,
                                         const float* __restrict__ wt,
                                         int tb0, int lq, int kcol, int lane,
                                         float acc[8][8]) {
#pragma unroll
    for (int s = 0; s < 8; s++) {
        const int kb = s * 8;
        u32 a[2][4];
#pragma unroll
        for (int mt = 0; mt < 2; mt++) {
            const float* p = BUF + (tb0 + 16 * mt + lq) * PBN + kb + kcol;
            a[mt][0] = cvt_tf32(p[0]);
            a[mt][1] = cvt_tf32(p[8 * PBN]);
            a[mt][2] = cvt_tf32(p[4]);
            a[mt][3] = cvt_tf32(p[8 * PBN + 4]);
        }
        const uint2* wp = (const uint2*)(wt + s * 512) + lane;
#pragma unroll
        for (int nt = 0; nt < 8; nt++) {
            uint2 b = wp[nt * 32];
            mma_tf32(&acc[nt][0], a[0][0], a[0][1], a[0][2], a[0][3], b.x, b.y);
            mma_tf32(&acc[nt][4], a[1][0], a[1][1], a[1][2], a[1][3], b.x, b.y);
        }
    }
}

// store D fragments into BUF [t][n] (pitch 76 -> bank-conflict-free)
__device__ __forceinline__ void stile_mma(float* __restrict__ BUF, int tb0,
                                          int lq, int kcol,
                                          const float acc[8][8]) {
#pragma unroll
    for (int nt = 0; nt < 8; nt++) {
        const int nc = nt * 8 + 2 * kcol;
#pragma unroll
        for (int mt = 0; mt < 2; mt++) {
            const int r0 = tb0 + 16 * mt + lq;
            *(ull*)(BUF + r0 * PBN + nc) = pk(acc[nt][4 * mt], acc[nt][4 * mt + 1]);
            *(ull*)(BUF + (r0 + 8) * PBN + nc) =
                pk(acc[nt][4 * mt + 2], acc[nt][4 * mt + 3]);
        }
    }
}

// ---------------------------------------------------------------------------
__global__ void __launch_bounds__(128)
k_prep(const float* __restrict__ Cm, const float* __restrict__ Wl,
       const float* __restrict__ Bm, const float* __restrict__ ga,
       const float* __restrict__ Win, const float* __restrict__ bl,
       const float* __restrict__ Wout) {
    const int b = blockIdx.x;
    const int tid = threadIdx.x;
    if (b == 12) {
        if (tid < 64) {
            const int n = tid;
            float a = 0.f;
#pragma unroll
            for (int k = 0; k < 64; k++) a = fmaf(Bm[n * 64 + k], Win[k], a);
            g_cX[n] = expf(ga[n]) * a;
            float w = 0.f;
#pragma unroll
            for (int j = 0; j < 64; j++)
                w = fmaf(Wout[j], Wl[3 * HH + j * 64 + n], w);
            g_wlo[n] = w;
            if (n == 0) {
                float s = 0.f;
#pragma unroll
                for (int j = 0; j < 64; j++) s = fmaf(Wout[j], bl[192 + j], s);
                g_aux[0] = s;
            }
        }
        return;
    }
    const int l = b / 3, m = b % 3;
    if (m == 2 && l == 3) return;
    __shared__ float gam[64];
    const float* src = (m == 0) ? Cm + l * HH
                     : (m == 1) ? Wl + l * HH
                                : Bm + (l + 1) * HH;
    u32* dst = (u32*)(g_wT + b * HH);
    if (m == 2) {
        if (tid < 64) gam[tid] = expf(ga[(l + 1) * 64 + tid]);
        __syncthreads();
    }
    for (int idx = tid; idx < HH; idx += 128) {
        const int c = idx & 1, ln = (idx >> 1) & 31;
        const int nt = (idx >> 6) & 7, s = idx >> 9;
        const int n = nt * 8 + (ln >> 2);
        const int k = s * 8 + (ln & 3) + 4 * c;
        float v = src[n * 64 + k];
        if (m == 2) v *= gam[n];
        dst[idx] = cvt_tf32(v);
    }
}

__global__ void __launch_bounds__(128)
k_init(const float* __restrict__ x, float* __restrict__ ends,
       const float* __restrict__ nu_log) {
    __shared__ __align__(16) float xs[TILE];
    const int tid = threadIdx.x;
    const int bc = blockIdx.x;
    const long tokbase = (long)(bc / CHUNKS) * T_ + (long)(bc % CHUNKS) * L_;

    float A = 0.f, a4 = 0.f, s = 0.f;
    if (tid < 64) {
        A = expf(-expf(nu_log[tid]));
        float a2 = A * A; a4 = a2 * a2;
    }
    for (int tl = 0; tl < NTIL; tl++) {
        __syncthreads();
        xs[tid] = x[tokbase + tl * TILE + tid];
        __syncthreads();
        if (tid < 64) {
#pragma unroll 8
            for (int q = 0; q < 32; q++) {
                float4 v = *(const float4*)(xs + 4 * q);
                float p2 = fmaf(A, v.x, v.y);
                float p3 = fmaf(A, p2, v.z);
                float p4 = fmaf(A, p3, v.w);
                s = fmaf(a4, s, p4);
            }
        }
    }
    if (tid < 64) ends[bc * 64 + tid] = g_cX[tid] * s;
}

__global__ void __launch_bounds__(128)
k_combine(const float* __restrict__ ends, float* __restrict__ carries,
          const float* __restrict__ nu_log) {
    __shared__ float es[CHUNKS * 64];
    const int b = blockIdx.x;
    const int tid = threadIdx.x;
    for (int i = tid; i < CHUNKS * 64; i += 128)
        es[i] = ends[b * CHUNKS * 64 + i];
    __syncthreads();
    if (tid < 64) {
        const int n = tid;
        const float AL = expf(-expf(nu_log[n]) * (float)L_);
        float carry = 0.f;
#pragma unroll 8
        for (int c = 0; c < CHUNKS; c++) {
            carries[(b * CHUNKS + c) * 64 + n] = carry;
            carry = fmaf(AL, carry, es[c * 64 + n]);
        }
    }
}

// ---------------------------------------------------------------------------
// Fused per-layer kernel, tensor-core GEMMs. Activations (u, bu) live in gmem
// in FRAGMENT layout (per warp, lane-major float4 pairs) so producers store
// straight from D-fragments and consumers load coalesced.
// ---------------------------------------------------------------------------
#define SM_BUF  0
#define SM_W    9728          // 2 slots x 4096 floats
#define SM_XS   17920
#define SM_DV   18048
#define SM_BL   18112
#define SM_W2   18176
#define SM_WLO  18240
#define SM_AUX  18304
#define SM_CX   18308
#define SMEMF   18376
#define SMEMB   (SMEMF * 4)

template <int MODE, int REV>
__global__ void __launch_bounds__(128, 3)
k_apply(const float* __restrict__ xin, const float* __restrict__ uin,
        float* __restrict__ uout, float* __restrict__ bu,
        const float* __restrict__ carr, float* __restrict__ ends,
        const float* __restrict__ wtC, const float* __restrict__ wtW,
        const float* __restrict__ wtB,
        const float* __restrict__ Dv, const float* __restrict__ bl,
        const float* __restrict__ nu_log, const float* __restrict__ Win,
        const float* __restrict__ Wout, const float* __restrict__ nu_nx) {
    extern __shared__ __align__(16) float sm[];
    float* BUF = sm + SM_BUF;
    float* WSL = sm + SM_W;
    float* XS  = sm + SM_XS;
    float* DVs = sm + SM_DV;
    float* BLs = sm + SM_BL;
    float* W2s = sm + SM_W2;
    float* WLO = sm + SM_WLO;
    float* AUX = sm + SM_AUX;
    float* CXs = sm + SM_CX;

    const int tid = threadIdx.x;
    const int lane = tid & 31;
    const int lq = lane >> 2, kcol = lane & 3;
    const int w = tid >> 5;
    const int tb0 = w * 32;
    const int bc = REV ? (int)(gridDim.x - 1 - blockIdx.x) : (int)blockIdx.x;
    const long tokbase = (long)(bc / CHUNKS) * T_ + (long)(bc % CHUNKS) * L_;
    const u32 wS0 = (u32)__cvta_generic_to_shared(WSL);

    stage16k(wS0, wtC, tid);
    int cur = 0;

    if (tid < 64) {
        DVs[tid] = Dv[tid];
        BLs[tid] = bl[tid];
        W2s[tid] = (MODE == 0) ? Win[tid] : ((MODE == 2) ? Wout[tid] : 0.f);
        if (MODE == 0) CXs[tid] = g_cX[tid];
        if (MODE == 2) WLO[tid] = g_wlo[tid];
        if (MODE == 2 && tid == 0) AUX[0] = g_aux[0];
    }
    float A1 = 0.f, a2 = 0.f, a3 = 0.f, a4 = 0.f, h = 0.f;
    float b4 = 0.f, A2n = 0.f, s = 0.f;
    if (tid < 64) {
        A1 = expf(-expf(nu_log[tid]));
        a2 = A1 * A1; a3 = a2 * A1; a4 = a2 * a2;
        h = carr[bc * 64 + tid];
        if (MODE != 2) {
            A2n = expf(-expf(nu_nx[tid]));
            float t2 = A2n * A2n; b4 = t2 * t2;
        }
    }
    cpwait();
    __syncthreads();

    for (int tl = 0; tl < NTIL; tl++) {
        __syncthreads();
        const size_t toff = ((size_t)bc * NTIL + tl) * (64 * TILE);
        const long tokb = tokbase + (long)tl * TILE;

        if (MODE == 0) {
            XS[tid] = xin[tokb + tid];
            __syncthreads();
#pragma unroll
            for (int it = 0; it < 16; it++) {
                int idx = it * 512 + tid * 4;
                int t = idx >> 6, n = idx & 63;
                float xv = XS[t];
                float4 c = *(const float4*)(CXs + n);
                *(float4*)(BUF + t * PBN + n) =
                    make_float4(xv * c.x, xv * c.y, xv * c.z, xv * c.w);
            }
        } else {
            // bu is fragment-layout: coalesced LDG.128 + bank-perfect STS.64
#pragma unroll
            for (int j = 0; j < 16; j++) {
                const int nt = j >> 1, mt = j & 1;
                float4 v = *(const float4*)(bu + fragoff(toff, w, j, lane));
                const int r0 = tb0 + 16 * mt + lq;
                const int nc = nt * 8 + 2 * kcol;
                *(ull*)(BUF + r0 * PBN + nc) = pk(v.x, v.y);
                *(ull*)(BUF + (r0 + 8) * PBN + nc) = pk(v.z, v.w);
            }
        }
        __syncthreads();

        // quad-Horner scan over [t][n] columns: BUF <- hprev
        if (tid < 64) {
            float* p = BUF + tid;
#pragma unroll 4
            for (int q = 0; q < 32; q++) {
                float* r = p + 4 * q * PBN;
                float v0 = r[0], v1 = r[PBN], v2 = r[2 * PBN], v3 = r[3 * PBN];
                float p2 = fmaf(A1, v0, v1);
                float p3 = fmaf(A1, p2, v2);
                float p4 = fmaf(A1, p3, v3);
                r[0] = h;
                r[PBN] = fmaf(A1, h, v0);
                r[2 * PBN] = fmaf(a2, h, p2);
                r[3 * PBN] = fmaf(a3, h, p3);
                h = fmaf(a4, h, p4);
            }
        }
        __syncthreads();

        // GEMM1: y = hprev @ Cm^T ; prefetch wtW
        if (MODE != 2) stage16k(wS0 + (cur ^ 1) * 16384, wtW, tid);
        float acc[8][8];
#pragma unroll
        for (int nt = 0; nt < 8; nt++)
#pragma unroll
            for (int j = 0; j < 8; j++) acc[nt][j] = 0.f;
        gemm_mma(BUF, WSL + cur * 4096, tb0, lq, kcol, lane, acc);

        // epilogue: z = tanh~(y + Dv*u)
#pragma unroll
        for (int nt = 0; nt < 8; nt++) {
            const int nc = nt * 8 + 2 * kcol;
            const ull dv2 = *(const ull*)(DVs + nc);
#pragma unroll
            for (int mt = 0; mt < 2; mt++) {
                ull u0, u1;
                if (MODE == 0) {
                    const int r0 = tb0 + 16 * mt + lq;
                    const ull w2 = *(const ull*)(W2s + nc);
                    u0 = mul2(dup2(XS[r0]), w2);
                    u1 = mul2(dup2(XS[r0 + 8]), w2);
                } else {
                    float4 uu = *(const float4*)(uin +
                                                 fragoff(toff, w, nt * 2 + mt, lane));
                    u0 = pk(uu.x, uu.y);
                    u1 = pk(uu.z, uu.w);
                }
                ull y0 = pk(acc[nt][4 * mt], acc[nt][4 * mt + 1]);
                ull y1 = pk(acc[nt][4 * mt + 2], acc[nt][4 * mt + 3]);
                fma2(y0, dv2, u0);
                fma2(y1, dv2, u1);
                float2 f0 = unp(y0), f1 = unp(y1);
                acc[nt][4 * mt]     = f0.x * rsqrtf(fmaf(f0.x, f0.x, 1.0f));
                acc[nt][4 * mt + 1] = f0.y * rsqrtf(fmaf(f0.y, f0.y, 1.0f));
                acc[nt][4 * mt + 2] = f1.x * rsqrtf(fmaf(f1.x, f1.x, 1.0f));
                acc[nt][4 * mt + 3] = f1.y * rsqrtf(fmaf(f1.y, f1.y, 1.0f));
            }
        }

        if (MODE == 2) {
            // out[t] = AUX + WLO.z[t] + Wout.u[t] straight from fragments
            float part[2][2] = {{0.f, 0.f}, {0.f, 0.f}};
#pragma unroll
            for (int nt = 0; nt < 8; nt++) {
                const int nc = nt * 8 + 2 * kcol;
                const float2 wl = *(const float2*)(WLO + nc);
                const float2 wo = *(const float2*)(W2s + nc);
#pragma unroll
                for (int mt = 0; mt < 2; mt++) {
                    float4 uu = *(const float4*)(uin +
                                                 fragoff(toff, w, nt * 2 + mt, lane));
                    part[mt][0] = fmaf(wl.x, acc[nt][4 * mt], part[mt][0]);
                    part[mt][0] = fmaf(wl.y, acc[nt][4 * mt + 1], part[mt][0]);
                    part[mt][0] = fmaf(wo.x, uu.x, part[mt][0]);
                    part[mt][0] = fmaf(wo.y, uu.y, part[mt][0]);
                    part[mt][1] = fmaf(wl.x, acc[nt][4 * mt + 2], part[mt][1]);
                    part[mt][1] = fmaf(wl.y, acc[nt][4 * mt + 3], part[mt][1]);
                    part[mt][1] = fmaf(wo.x, uu.z, part[mt][1]);
                    part[mt][1] = fmaf(wo.y, uu.w, part[mt][1]);
                }
            }
#pragma unroll
            for (int mt = 0; mt < 2; mt++)
#pragma unroll
                for (int hf = 0; hf < 2; hf++) {
                    float p = part[mt][hf];
                    p += __shfl_xor_sync(0xffffffffu, p, 1);
                    p += __shfl_xor_sync(0xffffffffu, p, 2);
                    if (kcol == 0)
                        uout[tokb + tb0 + 16 * mt + lq + 8 * hf] = AUX[0] + p;
                }
            continue;
        }

        cpwait();
        __syncthreads();
        stile_mma(BUF, tb0, lq, kcol, acc);   // BUF <- z
        __syncthreads();
        cur ^= 1;

        // GEMM2: o = z @ Wl^T + bl + u ; prefetch wtB
        stage16k(wS0 + (cur ^ 1) * 16384, wtB, tid);
#pragma unroll
        for (int nt = 0; nt < 8; nt++)
#pragma unroll
            for (int j = 0; j < 8; j++) acc[nt][j] = 0.f;
        gemm_mma(BUF, WSL + cur * 4096, tb0, lq, kcol, lane, acc);
#pragma unroll
        for (int nt = 0; nt < 8; nt++) {
            const int nc = nt * 8 + 2 * kcol;
            const ull bl2 = *(const ull*)(BLs + nc);
#pragma unroll
            for (int mt = 0; mt < 2; mt++) {
                ull u0, u1;
                if (MODE == 0) {
                    const int r0 = tb0 + 16 * mt + lq;
                    const ull w2 = *(const ull*)(W2s + nc);
                    u0 = mul2(dup2(XS[r0]), w2);
                    u1 = mul2(dup2(XS[r0 + 8]), w2);
                } else {
                    float4 uu = *(const float4*)(uin +
                                                 fragoff(toff, w, nt * 2 + mt, lane));
                    u0 = pk(uu.x, uu.y);
                    u1 = pk(uu.z, uu.w);
                }
                ull y0 = pk(acc[nt][4 * mt], acc[nt][4 * mt + 1]);
                ull y1 = pk(acc[nt][4 * mt + 2], acc[nt][4 * mt + 3]);
                y0 = add2(y0, add2(u0, bl2));
                y1 = add2(y1, add2(u1, bl2));
                float2 f0 = unp(y0), f1 = unp(y1);
                acc[nt][4 * mt] = f0.x;     acc[nt][4 * mt + 1] = f0.y;
                acc[nt][4 * mt + 2] = f1.x; acc[nt][4 * mt + 3] = f1.y;
                // direct fragment-layout store of u_next (coalesced STG.128)
                *(float4*)(uout + fragoff(toff, w, nt * 2 + mt, lane)) =
                    make_float4(f0.x, f0.y, f1.x, f1.y);
            }
        }
        cpwait();
        __syncthreads();
        stile_mma(BUF, tb0, lq, kcol, acc);   // BUF <- u_next (GEMM3's A)
        __syncthreads();
        cur ^= 1;

        // GEMM3: Bu_next = u_next @ (g*Bm)^T ; prefetch wtC
        stage16k(wS0 + (cur ^ 1) * 16384, wtC, tid);
#pragma unroll
        for (int nt = 0; nt < 8; nt++)
#pragma unroll
            for (int j = 0; j < 8; j++) acc[nt][j] = 0.f;
        gemm_mma(BUF, WSL + cur * 4096, tb0, lq, kcol, lane, acc);
        // direct fragment-layout store of Bu_next
#pragma unroll
        for (int nt = 0; nt < 8; nt++)
#pragma unroll
            for (int mt = 0; mt < 2; mt++)
                *(float4*)(bu + fragoff(toff, w, nt * 2 + mt, lane)) =
                    make_float4(acc[nt][4 * mt], acc[nt][4 * mt + 1],
                                acc[nt][4 * mt + 2], acc[nt][4 * mt + 3]);
        cpwait();
        __syncthreads();
        stile_mma(BUF, tb0, lq, kcol, acc);   // BUF <- Bu_next (for ends scan)
        __syncthreads();
        cur ^= 1;

        // chunk end-state for next layer (quad-Horner over columns)
        if (tid < 64) {
            const float* p = BUF + tid;
#pragma unroll 4
            for (int q = 0; q < 32; q++) {
                const float* r = p + 4 * q * PBN;
                float p2 = fmaf(A2n, r[0], r[PBN]);
                float p3 = fmaf(A2n, p2, r[2 * PBN]);
                float p4 = fmaf(A2n, p3, r[3 * PBN]);
                s = fmaf(b4, s, p4);
            }
        }
    }
    if (MODE != 2 && tid < 64) ends[bc * 64 + tid] = s;
}

// ---------------------------------------------------------------------------
extern "C" void kernel_launch(void* const* d_in, const int* in_sizes, int n_in,
                              void* d_out, int out_size) {
    (void)in_sizes; (void)n_in; (void)out_size;
    const float* x   = (const float*)d_in[0];
    const float* Win = (const float*)d_in[1];
    const float* nu  = (const float*)d_in[2];
    const float* ga  = (const float*)d_in[3];
    const float* Bm  = (const float*)d_in[4];
    const float* Cm  = (const float*)d_in[5];
    const float* Dv  = (const float*)d_in[6];
    const float* Wl  = (const float*)d_in[7];
    const float* bl  = (const float*)d_in[8];
    const float* Wo  = (const float*)d_in[9];
    float* out = (float*)d_out;

    float *u, *bu, *ends, *carr, *wT;
    cudaGetSymbolAddress((void**)&u, g_u);
    cudaGetSymbolAddress((void**)&bu, g_bu);
    cudaGetSymbolAddress((void**)&ends, g_ends);
    cudaGetSymbolAddress((void**)&carr, g_carr);
    cudaGetSymbolAddress((void**)&wT, g_wT);

    static int inited = 0;
    if (!inited) {
        cudaFuncSetAttribute(k_apply<0,0>, cudaFuncAttributeMaxDynamicSharedMemorySize, SMEMB);
        cudaFuncSetAttribute(k_apply<1,1>, cudaFuncAttributeMaxDynamicSharedMemorySize, SMEMB);
        cudaFuncSetAttribute(k_apply<1,0>, cudaFuncAttributeMaxDynamicSharedMemorySize, SMEMB);
        cudaFuncSetAttribute(k_apply<2,1>, cudaFuncAttributeMaxDynamicSharedMemorySize, SMEMB);
        inited = 1;
    }

    const dim3 grid(B_ * CHUNKS), blk(128);

    k_prep<<<13, 128>>>(Cm, Wl, Bm, ga, Win, bl, Wo);
    k_init<<<grid, blk>>>(x, ends, nu);
    k_combine<<<B_, 128>>>(ends, carr, nu);
    k_apply<0,0><<<grid, blk, SMEMB>>>(x, u, u, bu, carr, ends,
                                       wT + 0 * HH, wT + 1 * HH, wT + 2 * HH,
                                       Dv, bl, nu, Win, Wo, nu + 64);
    k_combine<<<B_, 128>>>(ends, carr, nu + 64);
    k_apply<1,1><<<grid, blk, SMEMB>>>(x, u, u, bu, carr, ends,
                                       wT + 3 * HH, wT + 4 * HH, wT + 5 * HH,
                                       Dv + 64, bl + 64, nu + 64, Win, Wo,
                                       nu + 128);
    k_combine<<<B_, 128>>>(ends, carr, nu + 128);
    k_apply<1,0><<<grid, blk, SMEMB>>>(x, u, u, bu, carr, ends,
                                       wT + 6 * HH, wT + 7 * HH, wT + 8 * HH,
                                       Dv + 128, bl + 128, nu + 128, Win, Wo,
                                       nu + 192);
    k_combine<<<B_, 128>>>(ends, carr, nu + 192);
    k_apply<2,1><<<grid, blk, SMEMB>>>(x, u, out, bu, carr, ends,
                                       wT + 9 * HH, wT + 9 * HH, wT + 9 * HH,
                                       Dv + 192, bl + 192, nu + 192, Win, Wo,
                                       nu);
}

// round 12
// speedup vs baseline: 2.2954x; 1.0010x over previous
#include <cuda_runtime.h>
#include <cstdint>

#define B_     16
#define T_     65536
#define CHUNKS 128
#define TILE   128
#define NTIL   4
#define L_     512
#define PBN    76
#define HH     4096
typedef unsigned long long ull;
typedef unsigned int u32;

__device__ float g_u [(size_t)B_ * T_ * 64];
__device__ float g_bu[(size_t)B_ * T_ * 64];
__device__ float g_ends[B_ * CHUNKS * 64];
__device__ float g_carr[B_ * CHUNKS * 64];
__device__ float g_cX[64];
__device__ float g_wlo[64];
__device__ float g_aux[1];
__device__ float g_wT[12 * HH];   // fragment-packed tf32 weights

__device__ __forceinline__ void fma2(ull& d, ull a, ull b) {
    asm("fma.rn.f32x2 %0, %1, %2, %0;" : "+l"(d) : "l"(a), "l"(b));
}
__device__ __forceinline__ ull add2(ull a, ull b) {
    ull d; asm("add.rn.f32x2 %0, %1, %2;" : "=l"(d) : "l"(a), "l"(b)); return d;
}
__device__ __forceinline__ ull mul2(ull a, ull b) {
    ull d; asm("mul.rn.f32x2 %0, %1, %2;" : "=l"(d) : "l"(a), "l"(b)); return d;
}
__device__ __forceinline__ ull dup2(float x) {
    ull r; asm("mov.b64 %0, {%1, %1};" : "=l"(r) : "f"(x)); return r;
}
__device__ __forceinline__ float2 unp(ull p) {
    float2 r; asm("mov.b64 {%0, %1}, %2;" : "=f"(r.x), "=f"(r.y) : "l"(p)); return r;
}
__device__ __forceinline__ ull pk(float a, float b) {
    ull r; asm("mov.b64 %0, {%1, %2};" : "=l"(r) : "f"(a), "f"(b)); return r;
}
__device__ __forceinline__ u32 cvt_tf32(float x) {
    u32 r; asm("cvt.rna.tf32.f32 %0, %1;" : "=r"(r) : "f"(x)); return r;
}
__device__ __forceinline__ void mma_tf32(float* d, u32 a0, u32 a1, u32 a2,
                                         u32 a3, u32 b0, u32 b1) {
    asm volatile(
        "mma.sync.aligned.m16n8k8.row.col.f32.tf32.tf32.f32 "
        "{%0,%1,%2,%3}, {%4,%5,%6,%7}, {%8,%9}, {%0,%1,%2,%3};"
        : "+f"(d[0]), "+f"(d[1]), "+f"(d[2]), "+f"(d[3])
        : "r"(a0), "r"(a1), "r"(a2), "r"(a3), "r"(b0), "r"(b1));
}

__device__ __forceinline__ void stage16k(u32 dst, const float* __restrict__ src,
                                         int tid) {
#pragma unroll
    for (int j = 0; j < 8; j++) {
        asm volatile("cp.async.ca.shared.global [%0], [%1], 16;"
                     :: "r"(dst + tid * 16 + j * 2048),
                        "l"(src + tid * 4 + j * 512));
    }
    asm volatile("cp.async.commit_group;");
}
__device__ __forceinline__ void cpwait() {
    asm volatile("cp.async.wait_group 0;");
}

// fragment-layout gmem offset
__device__ __forceinline__ size_t fragoff(size_t toff, int w, int j, int lane) {
    return toff + (size_t)w * 2048 + (size_t)(j * 32 + lane) * 4;
}

// GEMM1: A from BUF [t][n] pitch 76
__device__ __forceinline__ void gemm_mma(const float* __restrict__ BUF,
                                         const float* __restrict__ wt,
                                         int tb0, int lq, int kcol, int lane,
                                         float acc[8][8]) {
#pragma unroll
    for (int s = 0; s < 8; s++) {
        const int kb = s * 8;
        u32 a[2][4];
#pragma unroll
        for (int mt = 0; mt < 2; mt++) {
            const float* p = BUF + (tb0 + 16 * mt + lq) * PBN + kb + kcol;
            a[mt][0] = cvt_tf32(p[0]);
            a[mt][1] = cvt_tf32(p[8 * PBN]);
            a[mt][2] = cvt_tf32(p[4]);
            a[mt][3] = cvt_tf32(p[8 * PBN + 4]);
        }
        const uint2* wp = (const uint2*)(wt + s * 512) + lane;
#pragma unroll
        for (int nt = 0; nt < 8; nt++) {
            uint2 b = wp[nt * 32];
            mma_tf32(&acc[nt][0], a[0][0], a[0][1], a[0][2], a[0][3], b.x, b.y);
            mma_tf32(&acc[nt][4], a[1][0], a[1][1], a[1][2], a[1][3], b.x, b.y);
        }
    }
}

// GEMM with A sourced from previous GEMM's D-fragments via intra-quad shfl.
// D frag: col j of a row-quad lives in lane (lq, j>>1), reg parity j&1.
// A frag needs cols kcol and kcol+4.
__device__ __forceinline__ void gemm_frA(const float src[8][8],
                                         const float* __restrict__ wt,
                                         int lq, int kcol, int lane,
                                         float out[8][8]) {
    const bool par = (kcol & 1) != 0;
    const int src1 = (lq << 2) | (kcol >> 1);
    const int src2 = src1 + 2;
#pragma unroll
    for (int s = 0; s < 8; s++) {
        u32 a[2][4];
#pragma unroll
        for (int mt = 0; mt < 2; mt++) {
            float t0 = __shfl_sync(0xffffffffu, src[s][4 * mt + 0], src1);
            float t1 = __shfl_sync(0xffffffffu, src[s][4 * mt + 1], src1);
            float t2 = __shfl_sync(0xffffffffu, src[s][4 * mt + 2], src1);
            float t3 = __shfl_sync(0xffffffffu, src[s][4 * mt + 3], src1);
            float u0 = __shfl_sync(0xffffffffu, src[s][4 * mt + 0], src2);
            float u1 = __shfl_sync(0xffffffffu, src[s][4 * mt + 1], src2);
            float u2 = __shfl_sync(0xffffffffu, src[s][4 * mt + 2], src2);
            float u3 = __shfl_sync(0xffffffffu, src[s][4 * mt + 3], src2);
            a[mt][0] = cvt_tf32(par ? t1 : t0);
            a[mt][1] = cvt_tf32(par ? t3 : t2);
            a[mt][2] = cvt_tf32(par ? u1 : u0);
            a[mt][3] = cvt_tf32(par ? u3 : u2);
        }
        const uint2* wp = (const uint2*)(wt + s * 512) + lane;
#pragma unroll
        for (int nt = 0; nt < 8; nt++) {
            uint2 b = wp[nt * 32];
            mma_tf32(&out[nt][0], a[0][0], a[0][1], a[0][2], a[0][3], b.x, b.y);
            mma_tf32(&out[nt][4], a[1][0], a[1][1], a[1][2], a[1][3], b.x, b.y);
        }
    }
}

// store D fragments into BUF [t][n]
__device__ __forceinline__ void stile_mma(float* __restrict__ BUF, int tb0,
                                          int lq, int kcol,
                                          const float acc[8][8]) {
#pragma unroll
    for (int nt = 0; nt < 8; nt++) {
        const int nc = nt * 8 + 2 * kcol;
#pragma unroll
        for (int mt = 0; mt < 2; mt++) {
            const int r0 = tb0 + 16 * mt + lq;
            *(ull*)(BUF + r0 * PBN + nc) = pk(acc[nt][4 * mt], acc[nt][4 * mt + 1]);
            *(ull*)(BUF + (r0 + 8) * PBN + nc) =
                pk(acc[nt][4 * mt + 2], acc[nt][4 * mt + 3]);
        }
    }
}

// ---------------------------------------------------------------------------
__global__ void __launch_bounds__(128)
k_prep(const float* __restrict__ Cm, const float* __restrict__ Wl,
       const float* __restrict__ Bm, const float* __restrict__ ga,
       const float* __restrict__ Win, const float* __restrict__ bl,
       const float* __restrict__ Wout) {
    const int b = blockIdx.x;
    const int tid = threadIdx.x;
    if (b == 12) {
        if (tid < 64) {
            const int n = tid;
            float a = 0.f;
#pragma unroll
            for (int k = 0; k < 64; k++) a = fmaf(Bm[n * 64 + k], Win[k], a);
            g_cX[n] = expf(ga[n]) * a;
            float w = 0.f;
#pragma unroll
            for (int j = 0; j < 64; j++)
                w = fmaf(Wout[j], Wl[3 * HH + j * 64 + n], w);
            g_wlo[n] = w;
            if (n == 0) {
                float s = 0.f;
#pragma unroll
                for (int j = 0; j < 64; j++) s = fmaf(Wout[j], bl[192 + j], s);
                g_aux[0] = s;
            }
        }
        return;
    }
    const int l = b / 3, m = b % 3;
    if (m == 2 && l == 3) return;
    __shared__ float gam[64];
    const float* src = (m == 0) ? Cm + l * HH
                     : (m == 1) ? Wl + l * HH
                                : Bm + (l + 1) * HH;
    u32* dst = (u32*)(g_wT + b * HH);
    if (m == 2) {
        if (tid < 64) gam[tid] = expf(ga[(l + 1) * 64 + tid]);
        __syncthreads();
    }
    for (int idx = tid; idx < HH; idx += 128) {
        const int c = idx & 1, ln = (idx >> 1) & 31;
        const int nt = (idx >> 6) & 7, s = idx >> 9;
        const int n = nt * 8 + (ln >> 2);
        const int k = s * 8 + (ln & 3) + 4 * c;
        float v = src[n * 64 + k];
        if (m == 2) v *= gam[n];
        dst[idx] = cvt_tf32(v);
    }
}

__global__ void __launch_bounds__(128)
k_init(const float* __restrict__ x, float* __restrict__ ends,
       const float* __restrict__ nu_log) {
    __shared__ __align__(16) float xs[TILE];
    const int tid = threadIdx.x;
    const int bc = blockIdx.x;
    const long tokbase = (long)(bc / CHUNKS) * T_ + (long)(bc % CHUNKS) * L_;

    float A = 0.f, a4 = 0.f, s = 0.f;
    if (tid < 64) {
        A = expf(-expf(nu_log[tid]));
        float a2 = A * A; a4 = a2 * a2;
    }
    for (int tl = 0; tl < NTIL; tl++) {
        __syncthreads();
        xs[tid] = x[tokbase + tl * TILE + tid];
        __syncthreads();
        if (tid < 64) {
#pragma unroll 8
            for (int q = 0; q < 32; q++) {
                float4 v = *(const float4*)(xs + 4 * q);
                float p2 = fmaf(A, v.x, v.y);
                float p3 = fmaf(A, p2, v.z);
                float p4 = fmaf(A, p3, v.w);
                s = fmaf(a4, s, p4);
            }
        }
    }
    if (tid < 64) ends[bc * 64 + tid] = g_cX[tid] * s;
}

__global__ void __launch_bounds__(128)
k_combine(const float* __restrict__ ends, float* __restrict__ carries,
          const float* __restrict__ nu_log) {
    __shared__ float es[CHUNKS * 64];
    const int b = blockIdx.x;
    const int tid = threadIdx.x;
    for (int i = tid; i < CHUNKS * 64; i += 128)
        es[i] = ends[b * CHUNKS * 64 + i];
    __syncthreads();
    if (tid < 64) {
        const int n = tid;
        const float AL = expf(-expf(nu_log[n]) * (float)L_);
        float carry = 0.f;
#pragma unroll 8
        for (int c = 0; c < CHUNKS; c++) {
            carries[(b * CHUNKS + c) * 64 + n] = carry;
            carry = fmaf(AL, carry, es[c * 64 + n]);
        }
    }
}

// ---------------------------------------------------------------------------
// Fused per-layer kernel, tensor-core GEMMs with register fragment
// pass-through (z and u_next never touch shared memory).
// ---------------------------------------------------------------------------
#define SM_BUF  0
#define SM_W    9728          // 2 slots x 4096 floats
#define SM_XS   17920
#define SM_DV   18048
#define SM_BL   18112
#define SM_W2   18176
#define SM_WLO  18240
#define SM_AUX  18304
#define SM_CX   18308
#define SMEMF   18376
#define SMEMB   (SMEMF * 4)

template <int MODE, int REV>
__global__ void __launch_bounds__(128, 3)
k_apply(const float* __restrict__ xin, const float* __restrict__ uin,
        float* __restrict__ uout, float* __restrict__ bu,
        const float* __restrict__ carr, float* __restrict__ ends,
        const float* __restrict__ wtC, const float* __restrict__ wtW,
        const float* __restrict__ wtB,
        const float* __restrict__ Dv, const float* __restrict__ bl,
        const float* __restrict__ nu_log, const float* __restrict__ Win,
        const float* __restrict__ Wout, const float* __restrict__ nu_nx) {
    extern __shared__ __align__(16) float sm[];
    float* BUF = sm + SM_BUF;
    float* WSL = sm + SM_W;
    float* XS  = sm + SM_XS;
    float* DVs = sm + SM_DV;
    float* BLs = sm + SM_BL;
    float* W2s = sm + SM_W2;
    float* WLO = sm + SM_WLO;
    float* AUX = sm + SM_AUX;
    float* CXs = sm + SM_CX;

    const int tid = threadIdx.x;
    const int lane = tid & 31;
    const int lq = lane >> 2, kcol = lane & 3;
    const int w = tid >> 5;
    const int tb0 = w * 32;
    const int bc = REV ? (int)(gridDim.x - 1 - blockIdx.x) : (int)blockIdx.x;
    const long tokbase = (long)(bc / CHUNKS) * T_ + (long)(bc % CHUNKS) * L_;
    const u32 wS0 = (u32)__cvta_generic_to_shared(WSL);

    stage16k(wS0, wtC, tid);
    int cur = 0;

    if (tid < 64) {
        DVs[tid] = Dv[tid];
        BLs[tid] = bl[tid];
        W2s[tid] = (MODE == 0) ? Win[tid] : ((MODE == 2) ? Wout[tid] : 0.f);
        if (MODE == 0) CXs[tid] = g_cX[tid];
        if (MODE == 2) WLO[tid] = g_wlo[tid];
        if (MODE == 2 && tid == 0) AUX[0] = g_aux[0];
    }
    float A1 = 0.f, a2 = 0.f, a3 = 0.f, a4 = 0.f, h = 0.f;
    float b4 = 0.f, A2n = 0.f, s = 0.f;
    if (tid < 64) {
        A1 = expf(-expf(nu_log[tid]));
        a2 = A1 * A1; a3 = a2 * A1; a4 = a2 * a2;
        h = carr[bc * 64 + tid];
        if (MODE != 2) {
            A2n = expf(-expf(nu_nx[tid]));
            float t2 = A2n * A2n; b4 = t2 * t2;
        }
    }
    cpwait();
    __syncthreads();

    for (int tl = 0; tl < NTIL; tl++) {
        __syncthreads();   // #1: BUF safe vs prev ends-read; slot cur^1 free
        const size_t toff = ((size_t)bc * NTIL + tl) * (64 * TILE);
        const long tokb = tokbase + (long)tl * TILE;

        if (MODE == 0) {
            XS[tid] = xin[tokb + tid];
            __syncthreads();
#pragma unroll
            for (int it = 0; it < 16; it++) {
                int idx = it * 512 + tid * 4;
                int t = idx >> 6, n = idx & 63;
                float xv = XS[t];
                float4 c = *(const float4*)(CXs + n);
                *(float4*)(BUF + t * PBN + n) =
                    make_float4(xv * c.x, xv * c.y, xv * c.z, xv * c.w);
            }
        } else {
#pragma unroll
            for (int j = 0; j < 16; j++) {
                const int nt = j >> 1, mt = j & 1;
                float4 v = *(const float4*)(bu + fragoff(toff, w, j, lane));
                const int r0 = tb0 + 16 * mt + lq;
                const int nc = nt * 8 + 2 * kcol;
                *(ull*)(BUF + r0 * PBN + nc) = pk(v.x, v.y);
                *(ull*)(BUF + (r0 + 8) * PBN + nc) = pk(v.z, v.w);
            }
        }
        __syncthreads();   // #2

        // quad-Horner scan over [t][n] columns: BUF <- hprev
        if (tid < 64) {
            float* p = BUF + tid;
#pragma unroll 4
            for (int q = 0; q < 32; q++) {
                float* r = p + 4 * q * PBN;
                float v0 = r[0], v1 = r[PBN], v2 = r[2 * PBN], v3 = r[3 * PBN];
                float p2 = fmaf(A1, v0, v1);
                float p3 = fmaf(A1, p2, v2);
                float p4 = fmaf(A1, p3, v3);
                r[0] = h;
                r[PBN] = fmaf(A1, h, v0);
                r[2 * PBN] = fmaf(a2, h, p2);
                r[3 * PBN] = fmaf(a3, h, p3);
                h = fmaf(a4, h, p4);
            }
        }
        __syncthreads();   // #3

        // GEMM1: y = hprev @ Cm^T ; prefetch wtW into idle slot
        if (MODE != 2) stage16k(wS0 + (cur ^ 1) * 16384, wtW, tid);
        float acc[8][8];
#pragma unroll
        for (int nt = 0; nt < 8; nt++)
#pragma unroll
            for (int j = 0; j < 8; j++) acc[nt][j] = 0.f;
        gemm_mma(BUF, WSL + cur * 4096, tb0, lq, kcol, lane, acc);

        // epilogue1: z = tanh~(y + Dv*u)  (in place in acc)
#pragma unroll
        for (int nt = 0; nt < 8; nt++) {
            const int nc = nt * 8 + 2 * kcol;
            const ull dv2 = *(const ull*)(DVs + nc);
#pragma unroll
            for (int mt = 0; mt < 2; mt++) {
                ull u0, u1;
                if (MODE == 0) {
                    const int r0 = tb0 + 16 * mt + lq;
                    const ull w2 = *(const ull*)(W2s + nc);
                    u0 = mul2(dup2(XS[r0]), w2);
                    u1 = mul2(dup2(XS[r0 + 8]), w2);
                } else {
                    float4 uu = *(const float4*)(uin +
                                                 fragoff(toff, w, nt * 2 + mt, lane));
                    u0 = pk(uu.x, uu.y);
                    u1 = pk(uu.z, uu.w);
                }
                ull y0 = pk(acc[nt][4 * mt], acc[nt][4 * mt + 1]);
                ull y1 = pk(acc[nt][4 * mt + 2], acc[nt][4 * mt + 3]);
                fma2(y0, dv2, u0);
                fma2(y1, dv2, u1);
                float2 f0 = unp(y0), f1 = unp(y1);
                acc[nt][4 * mt]     = f0.x * rsqrtf(fmaf(f0.x, f0.x, 1.0f));
                acc[nt][4 * mt + 1] = f0.y * rsqrtf(fmaf(f0.y, f0.y, 1.0f));
                acc[nt][4 * mt + 2] = f1.x * rsqrtf(fmaf(f1.x, f1.x, 1.0f));
                acc[nt][4 * mt + 3] = f1.y * rsqrtf(fmaf(f1.y, f1.y, 1.0f));
            }
        }

        if (MODE == 2) {
            float part[2][2] = {{0.f, 0.f}, {0.f, 0.f}};
#pragma unroll
            for (int nt = 0; nt < 8; nt++) {
                const int nc = nt * 8 + 2 * kcol;
                const float2 wl = *(const float2*)(WLO + nc);
                const float2 wo = *(const float2*)(W2s + nc);
#pragma unroll
                for (int mt = 0; mt < 2; mt++) {
                    float4 uu = *(const float4*)(uin +
                                                 fragoff(toff, w, nt * 2 + mt, lane));
                    part[mt][0] = fmaf(wl.x, acc[nt][4 * mt], part[mt][0]);
                    part[mt][0] = fmaf(wl.y, acc[nt][4 * mt + 1], part[mt][0]);
                    part[mt][0] = fmaf(wo.x, uu.x, part[mt][0]);
                    part[mt][0] = fmaf(wo.y, uu.y, part[mt][0]);
                    part[mt][1] = fmaf(wl.x, acc[nt][4 * mt + 2], part[mt][1]);
                    part[mt][1] = fmaf(wl.y, acc[nt][4 * mt + 3], part[mt][1]);
                    part[mt][1] = fmaf(wo.x, uu.z, part[mt][1]);
                    part[mt][1] = fmaf(wo.y, uu.w, part[mt][1]);
                }
            }
#pragma unroll
            for (int mt = 0; mt < 2; mt++)
#pragma unroll
                for (int hf = 0; hf < 2; hf++) {
                    float p = part[mt][hf];
                    p += __shfl_xor_sync(0xffffffffu, p, 1);
                    p += __shfl_xor_sync(0xffffffffu, p, 2);
                    if (kcol == 0)
                        uout[tokb + tb0 + 16 * mt + lq + 8 * hf] = AUX[0] + p;
                }
            continue;
        }

        cpwait();
        __syncthreads();   // #4: wtW staged everywhere; GEMM1 done with slot cur

        // GEMM2: o = z @ Wl^T + bl + u ; A via shfl from acc; prefetch wtB
        stage16k(wS0 + cur * 16384, wtB, tid);
        float acc2[8][8];
#pragma unroll
        for (int nt = 0; nt < 8; nt++)
#pragma unroll
            for (int j = 0; j < 8; j++) acc2[nt][j] = 0.f;
        gemm_frA(acc, WSL + (cur ^ 1) * 4096, lq, kcol, lane, acc2);
#pragma unroll
        for (int nt = 0; nt < 8; nt++) {
            const int nc = nt * 8 + 2 * kcol;
            const ull bl2 = *(const ull*)(BLs + nc);
#pragma unroll
            for (int mt = 0; mt < 2; mt++) {
                ull u0, u1;
                if (MODE == 0) {
                    const int r0 = tb0 + 16 * mt + lq;
                    const ull w2 = *(const ull*)(W2s + nc);
                    u0 = mul2(dup2(XS[r0]), w2);
                    u1 = mul2(dup2(XS[r0 + 8]), w2);
                } else {
                    float4 uu = *(const float4*)(uin +
                                                 fragoff(toff, w, nt * 2 + mt, lane));
                    u0 = pk(uu.x, uu.y);
                    u1 = pk(uu.z, uu.w);
                }
                ull y0 = pk(acc2[nt][4 * mt], acc2[nt][4 * mt + 1]);
                ull y1 = pk(acc2[nt][4 * mt + 2], acc2[nt][4 * mt + 3]);
                y0 = add2(y0, add2(u0, bl2));
                y1 = add2(y1, add2(u1, bl2));
                float2 f0 = unp(y0), f1 = unp(y1);
                acc2[nt][4 * mt] = f0.x;     acc2[nt][4 * mt + 1] = f0.y;
                acc2[nt][4 * mt + 2] = f1.x; acc2[nt][4 * mt + 3] = f1.y;
                *(float4*)(uout + fragoff(toff, w, nt * 2 + mt, lane)) =
                    make_float4(f0.x, f0.y, f1.x, f1.y);
            }
        }
        cpwait();
        __syncthreads();   // #5: wtB staged; GEMM2 done with slot cur^1

        // GEMM3: Bu_next = u_next @ (g*Bm)^T ; A via shfl from acc2;
        // prefetch next tile's wtC into slot cur^1
        stage16k(wS0 + (cur ^ 1) * 16384, wtC, tid);
#pragma unroll
        for (int nt = 0; nt < 8; nt++)
#pragma unroll
            for (int j = 0; j < 8; j++) acc[nt][j] = 0.f;
        gemm_frA(acc2, WSL + cur * 4096, lq, kcol, lane, acc);
#pragma unroll
        for (int nt = 0; nt < 8; nt++)
#pragma unroll
            for (int mt = 0; mt < 2; mt++)
                *(float4*)(bu + fragoff(toff, w, nt * 2 + mt, lane)) =
                    make_float4(acc[nt][4 * mt], acc[nt][4 * mt + 1],
                                acc[nt][4 * mt + 2], acc[nt][4 * mt + 3]);
        stile_mma(BUF, tb0, lq, kcol, acc);   // BUF <- Bu_next (for ends)
        cpwait();
        __syncthreads();   // #6: stile visible; wtC staged

        // chunk end-state for next layer (quad-Horner over columns)
        if (tid < 64) {
            const float* p = BUF + tid;
#pragma unroll 4
            for (int q = 0; q < 32; q++) {
                const float* r = p + 4 * q * PBN;
                float p2 = fmaf(A2n, r[0], r[PBN]);
                float p3 = fmaf(A2n, p2, r[2 * PBN]);
                float p4 = fmaf(A2n, p3, r[3 * PBN]);
                s = fmaf(b4, s, p4);
            }
        }
        cur ^= 1;
    }
    if (MODE != 2 && tid < 64) ends[bc * 64 + tid] = s;
}

// ---------------------------------------------------------------------------
extern "C" void kernel_launch(void* const* d_in, const int* in_sizes, int n_in,
                              void* d_out, int out_size) {
    (void)in_sizes; (void)n_in; (void)out_size;
    const float* x   = (const float*)d_in[0];
    const float* Win = (const float*)d_in[1];
    const float* nu  = (const float*)d_in[2];
    const float* ga  = (const float*)d_in[3];
    const float* Bm  = (const float*)d_in[4];
    const float* Cm  = (const float*)d_in[5];
    const float* Dv  = (const float*)d_in[6];
    const float* Wl  = (const float*)d_in[7];
    const float* bl  = (const float*)d_in[8];
    const float* Wo  = (const float*)d_in[9];
    float* out = (float*)d_out;

    float *u, *bu, *ends, *carr, *wT;
    cudaGetSymbolAddress((void**)&u, g_u);
    cudaGetSymbolAddress((void**)&bu, g_bu);
    cudaGetSymbolAddress((void**)&ends, g_ends);
    cudaGetSymbolAddress((void**)&carr, g_carr);
    cudaGetSymbolAddress((void**)&wT, g_wT);

    static int inited = 0;
    if (!inited) {
        cudaFuncSetAttribute(k_apply<0,0>, cudaFuncAttributeMaxDynamicSharedMemorySize, SMEMB);
        cudaFuncSetAttribute(k_apply<1,1>, cudaFuncAttributeMaxDynamicSharedMemorySize, SMEMB);
        cudaFuncSetAttribute(k_apply<1,0>, cudaFuncAttributeMaxDynamicSharedMemorySize, SMEMB);
        cudaFuncSetAttribute(k_apply<2,1>, cudaFuncAttributeMaxDynamicSharedMemorySize, SMEMB);
        inited = 1;
    }

    const dim3 grid(B_ * CHUNKS), blk(128);

    k_prep<<<13, 128>>>(Cm, Wl, Bm, ga, Win, bl, Wo);
    k_init<<<grid, blk>>>(x, ends, nu);
    k_combine<<<B_, 128>>>(ends, carr, nu);
    k_apply<0,0><<<grid, blk, SMEMB>>>(x, u, u, bu, carr, ends,
                                       wT + 0 * HH, wT + 1 * HH, wT + 2 * HH,
                                       Dv, bl, nu, Win, Wo, nu + 64);
    k_combine<<<B_, 128>>>(ends, carr, nu + 64);
    k_apply<1,1><<<grid, blk, SMEMB>>>(x, u, u, bu, carr, ends,
                                       wT + 3 * HH, wT + 4 * HH, wT + 5 * HH,
                                       Dv + 64, bl + 64, nu + 64, Win, Wo,
                                       nu + 128);
    k_combine<<<B_, 128>>>(ends, carr, nu + 128);
    k_apply<1,0><<<grid, blk, SMEMB>>>(x, u, u, bu, carr, ends,
                                       wT + 6 * HH, wT + 7 * HH, wT + 8 * HH,
                                       Dv + 128, bl + 128, nu + 128, Win, Wo,
                                       nu + 192);
    k_combine<<<B_, 128>>>(ends, carr, nu + 192);
    k_apply<2,1><<<grid, blk, SMEMB>>>(x, u, out, bu, carr, ends,
                                       wT + 9 * HH, wT + 9 * HH, wT + 9 * HH,
                                       Dv + 192, bl + 192, nu + 192, Win, Wo,
                                       nu);
}